// round 10
// baseline (speedup 1.0000x reference)
#include <cuda_runtime.h>
#include <cuda_fp16.h>
#include <cstdint>
#include <cstddef>

// Problem constants
#define Bn   8
#define Qn   900
#define En   256
#define NHn  8
#define HDn  32
#define NLn  4
#define NPn  4
#define Sn   19560
#define BQn  (Bn * Qn)          // 7200
#define Mv   (Bn * Sn)          // 156480

// Scratch (static device globals)
__device__ __half g_vh[(size_t)Bn * Sn * En];    // projected values [B,S,E] fp16
__device__ __half g_wt[(size_t)En * En];         // W_v^T fp16  [n][k]
__device__ float g_offlg[(size_t)BQn * 384];     // [off(256) | logits(128)] per row
__device__ float g_mid[(size_t)BQn * En];
__device__ float g_wc[(size_t)En * 384];         // W_off || W_attn  [k][384]
__device__ float g_bc[384];                      // b_off || b_attn

// ---------------------------------------------------------------------------
// W_v transpose + fp16 convert: Wt[n][k] = half(W[k][n]), 256x256.
// ---------------------------------------------------------------------------
__global__ void transpose_w_h(const float* __restrict__ W, __half* __restrict__ Wt)
{
    __shared__ float tile[32][33];
    const int bx = blockIdx.x * 32;   // n block
    const int by = blockIdx.y * 32;   // k block
    const int tx = threadIdx.x, ty = threadIdx.y;   // 32 x 8
#pragma unroll
    for (int i = 0; i < 32; i += 8)
        tile[ty + i][tx] = W[(size_t)(by + ty + i) * En + bx + tx];
    __syncthreads();
#pragma unroll
    for (int i = 0; i < 32; i += 8)
        Wt[(size_t)(bx + ty + i) * En + by + tx] = __float2half_rn(tile[tx][ty + i]);
}

// ---------------------------------------------------------------------------
// Weight concat: Wc[k][0..255]=W_off[k][:], Wc[k][256..383]=W_attn[k][:]
// FIX: battn indexed with (t-256) — previous OOB read was the round-4/9 bug.
// ---------------------------------------------------------------------------
__global__ void concat_wb(const float* __restrict__ Woff, const float* __restrict__ boff,
                          const float* __restrict__ Wattn, const float* __restrict__ battn,
                          float* __restrict__ Wc, float* __restrict__ bc)
{
    const int k = blockIdx.x;
    const int t = threadIdx.x;  // 384
    Wc[(size_t)k * 384 + t] = (t < 256) ? Woff[(size_t)k * 256 + t]
                                        : Wattn[(size_t)k * 128 + (t - 256)];
    if (k == 0) bc[t] = (t < 256) ? boff[t] : battn[t - 256];
}

// ---------------------------------------------------------------------------
// fp16 tensor-core GEMM (m16n8k16) for the value projection — round-8 proven.
// ---------------------------------------------------------------------------
__device__ __forceinline__ void mma_f16(float* c, const uint32_t* a, const uint32_t* b) {
    asm volatile(
        "mma.sync.aligned.m16n8k16.row.col.f32.f16.f16.f32 "
        "{%0,%1,%2,%3}, {%4,%5,%6,%7}, {%8,%9}, {%0,%1,%2,%3};"
        : "+f"(c[0]), "+f"(c[1]), "+f"(c[2]), "+f"(c[3])
        : "r"(a[0]), "r"(a[1]), "r"(a[2]), "r"(a[3]), "r"(b[0]), "r"(b[1]));
}

__global__ __launch_bounds__(256, 2)
void gemm_f16v(const float* __restrict__ A, const __half* __restrict__ Wt,
               const float* __restrict__ bias, __half* __restrict__ C,
               int M, int N, int K)
{
    __shared__ __half As[128][40];
    __shared__ __half Bsn[128][40];

    const int tid  = threadIdx.x;
    const int lane = tid & 31;
    const int wid  = tid >> 5;
    const int wm   = wid >> 2;
    const int wn   = wid & 3;
    const int g    = lane >> 2;
    const int tg   = lane & 3;
    const int m0   = blockIdx.y * 128;
    const int n0   = blockIdx.x * 128;

    float c[4][4][4];
#pragma unroll
    for (int i = 0; i < 4; i++)
#pragma unroll
        for (int j = 0; j < 4; j++)
#pragma unroll
            for (int r = 0; r < 4; r++) c[i][j][r] = 0.0f;

    const int a_kq = tid & 7;
    const int a_m  = tid >> 3;
    const int b_nr = tid >> 2;
    const int b_q  = tid & 3;

    for (int k0 = 0; k0 < K; k0 += 32) {
#pragma unroll
        for (int i = 0; i < 4; i++) {
            int m = a_m + 32 * i;
            float4 v = make_float4(0.f, 0.f, 0.f, 0.f);
            if (m0 + m < M) v = *(const float4*)(A + (size_t)(m0 + m) * K + k0 + a_kq * 4);
            __half2 h01 = __floats2half2_rn(v.x, v.y);
            __half2 h23 = __floats2half2_rn(v.z, v.w);
            uint2 pk;
            pk.x = *(uint32_t*)&h01;
            pk.y = *(uint32_t*)&h23;
            *(uint2*)&As[m][a_kq * 4] = pk;
        }
#pragma unroll
        for (int i = 0; i < 2; i++) {
            int n = b_nr + 64 * i;
            uint4 v = *(const uint4*)(Wt + (size_t)(n0 + n) * K + k0 + b_q * 8);
            *(uint4*)&Bsn[n][b_q * 8] = v;
        }
        __syncthreads();

#pragma unroll
        for (int kk = 0; kk < 2; kk++) {
            uint32_t a[4][4], b[4][2];
#pragma unroll
            for (int mf = 0; mf < 4; mf++) {
                int m = wm * 64 + mf * 16 + g;
                a[mf][0] = *(const uint32_t*)&As[m][kk * 16 + 2 * tg];
                a[mf][1] = *(const uint32_t*)&As[m + 8][kk * 16 + 2 * tg];
                a[mf][2] = *(const uint32_t*)&As[m][kk * 16 + 2 * tg + 8];
                a[mf][3] = *(const uint32_t*)&As[m + 8][kk * 16 + 2 * tg + 8];
            }
#pragma unroll
            for (int nf = 0; nf < 4; nf++) {
                int n = wn * 32 + nf * 8 + g;
                b[nf][0] = *(const uint32_t*)&Bsn[n][kk * 16 + 2 * tg];
                b[nf][1] = *(const uint32_t*)&Bsn[n][kk * 16 + 2 * tg + 8];
            }
#pragma unroll
            for (int mf = 0; mf < 4; mf++)
#pragma unroll
                for (int nf = 0; nf < 4; nf++)
                    mma_f16(c[mf][nf], a[mf], b[nf]);
        }
        __syncthreads();
    }

#pragma unroll
    for (int mf = 0; mf < 4; mf++) {
        const int r0 = m0 + wm * 64 + mf * 16 + g;
        const int r1 = r0 + 8;
#pragma unroll
        for (int nf = 0; nf < 4; nf++) {
            const int cb = n0 + wn * 32 + nf * 8 + 2 * tg;
            const float bx = bias[cb], by = bias[cb + 1];
            if (r0 < M) {
                __half2 o = __floats2half2_rn(c[mf][nf][0] + bx, c[mf][nf][1] + by);
                *(__half2*)(C + (size_t)r0 * N + cb) = o;
            }
            if (r1 < M) {
                __half2 o = __floats2half2_rn(c[mf][nf][2] + bx, c[mf][nf][3] + by);
                *(__half2*)(C + (size_t)r1 * N + cb) = o;
            }
        }
    }
}

// ---------------------------------------------------------------------------
// tf32 tensor-core GEMM with register-prefetch double buffering (round-9 code,
// now exonerated — the failure was the concat OOB).
// ---------------------------------------------------------------------------
__device__ __forceinline__ uint32_t f2tf32(float f) {
    uint32_t r;
    asm("cvt.rna.tf32.f32 %0, %1;" : "=r"(r) : "f"(f));
    return r;
}

__device__ __forceinline__ void mma_tf32(float* c, const uint32_t* a, const uint32_t* b) {
    asm volatile(
        "mma.sync.aligned.m16n8k8.row.col.f32.tf32.tf32.f32 "
        "{%0,%1,%2,%3}, {%4,%5,%6,%7}, {%8,%9}, {%0,%1,%2,%3};"
        : "+f"(c[0]), "+f"(c[1]), "+f"(c[2]), "+f"(c[3])
        : "r"(a[0]), "r"(a[1]), "r"(a[2]), "r"(a[3]), "r"(b[0]), "r"(b[1]));
}

__global__ __launch_bounds__(256, 1)
void gemm_tf32(const float* __restrict__ A, const float* __restrict__ Bw,
               const float* __restrict__ bias, const float* __restrict__ resid,
               float* __restrict__ C, int M, int N, int K)
{
    __shared__ uint32_t As[128][36];
    __shared__ uint32_t Bs[32][132];

    const int tid  = threadIdx.x;
    const int lane = tid & 31;
    const int wid  = tid >> 5;
    const int wm   = wid >> 2;
    const int wn   = wid & 3;
    const int g    = lane >> 2;
    const int tg   = lane & 3;
    const int m0   = blockIdx.y * 128;
    const int n0   = blockIdx.x * 128;

    float c[4][4][4];
#pragma unroll
    for (int i = 0; i < 4; i++)
#pragma unroll
        for (int j = 0; j < 4; j++)
#pragma unroll
            for (int r = 0; r < 4; r++) c[i][j][r] = 0.0f;

    const int a_kq = tid & 7;
    const int a_m  = tid >> 3;
    const int b_n4 = tid & 31;
    const int b_k  = tid >> 5;

    float4 pa[4], pb[4];

    // prefetch chunk 0
#pragma unroll
    for (int i = 0; i < 4; i++) {
        int m = a_m + 32 * i;
        pa[i] = make_float4(0.f, 0.f, 0.f, 0.f);
        if (m0 + m < M) pa[i] = *(const float4*)(A + (size_t)(m0 + m) * K + a_kq * 4);
        pb[i] = *(const float4*)(Bw + (size_t)(b_k + 8 * i) * N + n0 + b_n4 * 4);
    }

    const int NC = K / 32;
    for (int cidx = 0; cidx < NC; cidx++) {
#pragma unroll
        for (int i = 0; i < 4; i++) {
            uint4 t;
            t.x = f2tf32(pa[i].x); t.y = f2tf32(pa[i].y);
            t.z = f2tf32(pa[i].z); t.w = f2tf32(pa[i].w);
            *(uint4*)&As[a_m + 32 * i][a_kq * 4] = t;
            uint4 u;
            u.x = f2tf32(pb[i].x); u.y = f2tf32(pb[i].y);
            u.z = f2tf32(pb[i].z); u.w = f2tf32(pb[i].w);
            *(uint4*)&Bs[b_k + 8 * i][b_n4 * 4] = u;
        }
        __syncthreads();

        if (cidx + 1 < NC) {
            const int k0 = (cidx + 1) * 32;
#pragma unroll
            for (int i = 0; i < 4; i++) {
                int m = a_m + 32 * i;
                pa[i] = make_float4(0.f, 0.f, 0.f, 0.f);
                if (m0 + m < M)
                    pa[i] = *(const float4*)(A + (size_t)(m0 + m) * K + k0 + a_kq * 4);
                pb[i] = *(const float4*)(Bw + (size_t)(k0 + b_k + 8 * i) * N + n0 + b_n4 * 4);
            }
        }

#pragma unroll
        for (int kk = 0; kk < 4; kk++) {
            uint32_t a[4][4], b[4][2];
#pragma unroll
            for (int mf = 0; mf < 4; mf++) {
                int m = wm * 64 + mf * 16 + g;
                a[mf][0] = As[m][kk * 8 + tg];
                a[mf][1] = As[m + 8][kk * 8 + tg];
                a[mf][2] = As[m][kk * 8 + tg + 4];
                a[mf][3] = As[m + 8][kk * 8 + tg + 4];
            }
#pragma unroll
            for (int nf = 0; nf < 4; nf++) {
                int n = wn * 32 + nf * 8 + g;
                b[nf][0] = Bs[kk * 8 + tg][n];
                b[nf][1] = Bs[kk * 8 + tg + 4][n];
            }
#pragma unroll
            for (int mf = 0; mf < 4; mf++)
#pragma unroll
                for (int nf = 0; nf < 4; nf++)
                    mma_tf32(c[mf][nf], a[mf], b[nf]);
        }
        __syncthreads();
    }

#pragma unroll
    for (int mf = 0; mf < 4; mf++) {
        const int r0 = m0 + wm * 64 + mf * 16 + g;
        const int r1 = r0 + 8;
#pragma unroll
        for (int nf = 0; nf < 4; nf++) {
            const int cb = n0 + wn * 32 + nf * 8 + 2 * tg;
            const float bx = bias[cb], by = bias[cb + 1];
            if (r0 < M) {
                float2 o = make_float2(c[mf][nf][0] + bx, c[mf][nf][1] + by);
                if (resid) {
                    const float2 rr = *(const float2*)(resid + (size_t)r0 * N + cb);
                    o.x += rr.x; o.y += rr.y;
                }
                *(float2*)(C + (size_t)r0 * N + cb) = o;
            }
            if (r1 < M) {
                float2 o = make_float2(c[mf][nf][2] + bx, c[mf][nf][3] + by);
                if (resid) {
                    const float2 rr = *(const float2*)(resid + (size_t)r1 * N + cb);
                    o.x += rr.x; o.y += rr.y;
                }
                *(float2*)(C + (size_t)r1 * N + cb) = o;
            }
        }
    }
}

// ---------------------------------------------------------------------------
// Fused softmax + deformable sampling — proven; reads concat offlg (stride 384).
// ---------------------------------------------------------------------------
__global__ __launch_bounds__(256, 4)
void msda_sample(const float* __restrict__ offlg, const float* __restrict__ ref,
                 const __half* __restrict__ v, float* __restrict__ mid)
{
    const int lvlH[NLn]     = {92, 46, 23, 12};
    const int lvlW[NLn]     = {160, 80, 40, 20};
    const int lvlStart[NLn] = {0, 14720, 18400, 19320};

    const int row = blockIdx.x;
    const int b   = row / Qn;
    const int t   = threadIdx.x;

    __shared__ float s_loc[256];
    __shared__ float s_lg[128];
    __shared__ int4   s_idx[128];
    __shared__ float4 s_wgt[128];

    const float* __restrict__ rowp = offlg + (size_t)row * 384;

    {
        const int c = t & 1;
        const int l = (t >> 3) & 3;
        const float dim = (c == 0) ? (float)lvlW[l] : (float)lvlH[l];
        const float r = ref[((size_t)row * NLn + l) * 2 + c];
        s_loc[t] = r * dim - 0.5f + rowp[t];
    }
    if (t < 128) s_lg[t] = rowp[256 + t];
    __syncthreads();

    if (t < 128) {
        const int h = t >> 4;
        float m = -1e30f;
#pragma unroll
        for (int i = 0; i < 16; i++) m = fmaxf(m, s_lg[h * 16 + i]);
        float sum = 0.0f;
#pragma unroll
        for (int i = 0; i < 16; i++) sum += __expf(s_lg[h * 16 + i] - m);
        const float w = __expf(s_lg[t] - m) / sum;

        const int l = (t >> 2) & 3;
        const int Hl = lvlH[l], Wl = lvlW[l], base = lvlStart[l];
        const float x = s_loc[t * 2 + 0];
        const float y = s_loc[t * 2 + 1];
        const float xf = floorf(x), yf = floorf(y);
        const float wx = x - xf, wy = y - yf;
        const int x0 = (int)xf, y0 = (int)yf, x1 = x0 + 1, y1 = y0 + 1;

        const bool vx0 = (x0 >= 0) & (x0 < Wl), vx1 = (x1 >= 0) & (x1 < Wl);
        const bool vy0 = (y0 >= 0) & (y0 < Hl), vy1 = (y1 >= 0) & (y1 < Hl);
        const int xc0 = min(max(x0, 0), Wl - 1), xc1 = min(max(x1, 0), Wl - 1);
        const int yc0 = min(max(y0, 0), Hl - 1), yc1 = min(max(y1, 0), Hl - 1);

        int4 id;
        id.x = base + yc0 * Wl + xc0;
        id.y = base + yc0 * Wl + xc1;
        id.z = base + yc1 * Wl + xc0;
        id.w = base + yc1 * Wl + xc1;
        s_idx[t] = id;
        float4 ww;
        ww.x = (vy0 & vx0) ? w * (1.f - wy) * (1.f - wx) : 0.f;
        ww.y = (vy0 & vx1) ? w * (1.f - wy) * wx : 0.f;
        ww.z = (vy1 & vx0) ? w * wy * (1.f - wx) : 0.f;
        ww.w = (vy1 & vx1) ? w * wy * wx : 0.f;
        s_wgt[t] = ww;
    }
    __syncthreads();

    const int h = t >> 5;
    const int d = t & 31;
    const __half* __restrict__ vb = v + (size_t)b * Sn * En + h * HDn + d;

    float acc = 0.0f;
#pragma unroll
    for (int s = 0; s < 16; s++) {
        const int si = h * 16 + s;
        const int4   id = s_idx[si];
        const float4 ww = s_wgt[si];
        acc += ww.x * __half2float(vb[(size_t)id.x * En]);
        acc += ww.y * __half2float(vb[(size_t)id.y * En]);
        acc += ww.z * __half2float(vb[(size_t)id.z * En]);
        acc += ww.w * __half2float(vb[(size_t)id.w * En]);
    }

    mid[(size_t)row * En + t] = acc;
}

// ---------------------------------------------------------------------------
extern "C" void kernel_launch(void* const* d_in, const int* in_sizes, int n_in,
                              void* d_out, int out_size)
{
    const float* query  = (const float*)d_in[0];
    const float* value  = (const float*)d_in[1];
    const float* refpts = (const float*)d_in[2];
    const float* W_off  = (const float*)d_in[4];
    const float* b_off  = (const float*)d_in[5];
    const float* W_attn = (const float*)d_in[6];
    const float* b_attn = (const float*)d_in[7];
    const float* W_v    = (const float*)d_in[8];
    const float* b_v    = (const float*)d_in[9];
    const float* W_out  = (const float*)d_in[10];
    const float* b_out  = (const float*)d_in[11];
    float* out = (float*)d_out;

    void *pvh, *pwt, *polg, *pmid, *pwc, *pbc;
    cudaGetSymbolAddress(&pvh, g_vh);
    cudaGetSymbolAddress(&pwt, g_wt);
    cudaGetSymbolAddress(&polg, g_offlg);
    cudaGetSymbolAddress(&pmid, g_mid);
    cudaGetSymbolAddress(&pwc, g_wc);
    cudaGetSymbolAddress(&pbc, g_bc);
    __half* vh_s = (__half*)pvh;
    __half* wt_s = (__half*)pwt;
    float* olg_s = (float*)polg;
    float* mid_s = (float*)pmid;
    float* wc_s  = (float*)pwc;
    float* bc_s  = (float*)pbc;

    // 0a) transpose + fp16-convert W_v -> Wt[n][k]
    {
        dim3 grid(En / 32, En / 32);
        transpose_w_h<<<grid, dim3(32, 8)>>>(W_v, wt_s);
    }
    // 0b) concat offset/attn weights -> [256,384]
    concat_wb<<<En, 384>>>(W_off, b_off, W_attn, b_attn, wc_s, bc_s);

    // 1) value projection: [156480,256] @ [256,256]  (fp16 MMA, half output)
    {
        dim3 grid(En / 128, (Mv + 127) / 128);
        gemm_f16v<<<grid, 256>>>(value, wt_s, b_v, vh_s, Mv, En, En);
    }
    // 2) combined offset+logit projection: [7200,256] @ [256,384]  (tf32)
    {
        dim3 grid(384 / 128, (BQn + 127) / 128);
        gemm_tf32<<<grid, 256>>>(query, wc_s, bc_s, nullptr, olg_s, BQn, 384, En);
    }
    // 3) softmax + deformable bilinear sampling (fp16 gathers)
    msda_sample<<<BQn, 256>>>(olg_s, refpts, vh_s, mid_s);
    // 4) output projection + residual: [7200,256] @ [256,256] + query  (tf32)
    {
        dim3 grid(En / 128, (BQn + 127) / 128);
        gemm_tf32<<<grid, 256>>>(mid_s, W_out, b_out, query, out, BQn, En, En);
    }
}

// round 11
// speedup vs baseline: 1.6333x; 1.6333x over previous
#include <cuda_runtime.h>
#include <cuda_fp16.h>
#include <cstdint>
#include <cstddef>

// Problem constants
#define Bn   8
#define Qn   900
#define En   256
#define NHn  8
#define HDn  32
#define NLn  4
#define NPn  4
#define Sn   19560
#define BQn  (Bn * Qn)          // 7200
#define Mv   (Bn * Sn)          // 156480

// Scratch (static device globals)
__device__ __half g_vh[(size_t)Bn * Sn * En];    // projected values [B,S,E] fp16
__device__ __half g_wt[(size_t)En * En];         // W_v^T fp16  [n][k]
__device__ float g_offlg[(size_t)BQn * 384];     // [off(256) | logits(128)] per row
__device__ float g_mid[(size_t)BQn * En];
__device__ float g_wc[(size_t)En * 384];         // W_off || W_attn  [k][384]
__device__ float g_bc[384];                      // b_off || b_attn

// ---------------------------------------------------------------------------
// W_v transpose + fp16 convert: Wt[n][k] = half(W[k][n]), 256x256.
// ---------------------------------------------------------------------------
__global__ void transpose_w_h(const float* __restrict__ W, __half* __restrict__ Wt)
{
    __shared__ float tile[32][33];
    const int bx = blockIdx.x * 32;   // n block
    const int by = blockIdx.y * 32;   // k block
    const int tx = threadIdx.x, ty = threadIdx.y;   // 32 x 8
#pragma unroll
    for (int i = 0; i < 32; i += 8)
        tile[ty + i][tx] = W[(size_t)(by + ty + i) * En + bx + tx];
    __syncthreads();
#pragma unroll
    for (int i = 0; i < 32; i += 8)
        Wt[(size_t)(bx + ty + i) * En + by + tx] = __float2half_rn(tile[tx][ty + i]);
}

// ---------------------------------------------------------------------------
// Weight concat (FIXED battn index — proven in round 10).
// ---------------------------------------------------------------------------
__global__ void concat_wb(const float* __restrict__ Woff, const float* __restrict__ boff,
                          const float* __restrict__ Wattn, const float* __restrict__ battn,
                          float* __restrict__ Wc, float* __restrict__ bc)
{
    const int k = blockIdx.x;
    const int t = threadIdx.x;  // 384
    Wc[(size_t)k * 384 + t] = (t < 256) ? Woff[(size_t)k * 256 + t]
                                        : Wattn[(size_t)k * 128 + (t - 256)];
    if (k == 0) bc[t] = (t < 256) ? boff[t] : battn[t - 256];
}

// ---------------------------------------------------------------------------
// fp16 tensor-core GEMM (m16n8k16) for the value projection — round-8 proven.
// ---------------------------------------------------------------------------
__device__ __forceinline__ void mma_f16(float* c, const uint32_t* a, const uint32_t* b) {
    asm volatile(
        "mma.sync.aligned.m16n8k16.row.col.f32.f16.f16.f32 "
        "{%0,%1,%2,%3}, {%4,%5,%6,%7}, {%8,%9}, {%0,%1,%2,%3};"
        : "+f"(c[0]), "+f"(c[1]), "+f"(c[2]), "+f"(c[3])
        : "r"(a[0]), "r"(a[1]), "r"(a[2]), "r"(a[3]), "r"(b[0]), "r"(b[1]));
}

__global__ __launch_bounds__(256, 2)
void gemm_f16v(const float* __restrict__ A, const __half* __restrict__ Wt,
               const float* __restrict__ bias, __half* __restrict__ C,
               int M, int N, int K)
{
    __shared__ __half As[128][40];
    __shared__ __half Bsn[128][40];

    const int tid  = threadIdx.x;
    const int lane = tid & 31;
    const int wid  = tid >> 5;
    const int wm   = wid >> 2;
    const int wn   = wid & 3;
    const int g    = lane >> 2;
    const int tg   = lane & 3;
    const int m0   = blockIdx.y * 128;
    const int n0   = blockIdx.x * 128;

    float c[4][4][4];
#pragma unroll
    for (int i = 0; i < 4; i++)
#pragma unroll
        for (int j = 0; j < 4; j++)
#pragma unroll
            for (int r = 0; r < 4; r++) c[i][j][r] = 0.0f;

    const int a_kq = tid & 7;
    const int a_m  = tid >> 3;
    const int b_nr = tid >> 2;
    const int b_q  = tid & 3;

    for (int k0 = 0; k0 < K; k0 += 32) {
#pragma unroll
        for (int i = 0; i < 4; i++) {
            int m = a_m + 32 * i;
            float4 v = make_float4(0.f, 0.f, 0.f, 0.f);
            if (m0 + m < M) v = *(const float4*)(A + (size_t)(m0 + m) * K + k0 + a_kq * 4);
            __half2 h01 = __floats2half2_rn(v.x, v.y);
            __half2 h23 = __floats2half2_rn(v.z, v.w);
            uint2 pk;
            pk.x = *(uint32_t*)&h01;
            pk.y = *(uint32_t*)&h23;
            *(uint2*)&As[m][a_kq * 4] = pk;
        }
#pragma unroll
        for (int i = 0; i < 2; i++) {
            int n = b_nr + 64 * i;
            uint4 v = *(const uint4*)(Wt + (size_t)(n0 + n) * K + k0 + b_q * 8);
            *(uint4*)&Bsn[n][b_q * 8] = v;
        }
        __syncthreads();

#pragma unroll
        for (int kk = 0; kk < 2; kk++) {
            uint32_t a[4][4], b[4][2];
#pragma unroll
            for (int mf = 0; mf < 4; mf++) {
                int m = wm * 64 + mf * 16 + g;
                a[mf][0] = *(const uint32_t*)&As[m][kk * 16 + 2 * tg];
                a[mf][1] = *(const uint32_t*)&As[m + 8][kk * 16 + 2 * tg];
                a[mf][2] = *(const uint32_t*)&As[m][kk * 16 + 2 * tg + 8];
                a[mf][3] = *(const uint32_t*)&As[m + 8][kk * 16 + 2 * tg + 8];
            }
#pragma unroll
            for (int nf = 0; nf < 4; nf++) {
                int n = wn * 32 + nf * 8 + g;
                b[nf][0] = *(const uint32_t*)&Bsn[n][kk * 16 + 2 * tg];
                b[nf][1] = *(const uint32_t*)&Bsn[n][kk * 16 + 2 * tg + 8];
            }
#pragma unroll
            for (int mf = 0; mf < 4; mf++)
#pragma unroll
                for (int nf = 0; nf < 4; nf++)
                    mma_f16(c[mf][nf], a[mf], b[nf]);
        }
        __syncthreads();
    }

#pragma unroll
    for (int mf = 0; mf < 4; mf++) {
        const int r0 = m0 + wm * 64 + mf * 16 + g;
        const int r1 = r0 + 8;
#pragma unroll
        for (int nf = 0; nf < 4; nf++) {
            const int cb = n0 + wn * 32 + nf * 8 + 2 * tg;
            const float bx = bias[cb], by = bias[cb + 1];
            if (r0 < M) {
                __half2 o = __floats2half2_rn(c[mf][nf][0] + bx, c[mf][nf][1] + by);
                *(__half2*)(C + (size_t)r0 * N + cb) = o;
            }
            if (r1 < M) {
                __half2 o = __floats2half2_rn(c[mf][nf][2] + bx, c[mf][nf][3] + by);
                *(__half2*)(C + (size_t)r1 * N + cb) = o;
            }
        }
    }
}

// ---------------------------------------------------------------------------
// tf32 tensor-core GEMM — round-8 proven single-buffered version
// (register-prefetch variant reverted: 184 regs / issue-starved, measured slower).
// ---------------------------------------------------------------------------
__device__ __forceinline__ uint32_t f2tf32(float f) {
    uint32_t r;
    asm("cvt.rna.tf32.f32 %0, %1;" : "=r"(r) : "f"(f));
    return r;
}

__device__ __forceinline__ void mma_tf32(float* c, const uint32_t* a, const uint32_t* b) {
    asm volatile(
        "mma.sync.aligned.m16n8k8.row.col.f32.tf32.tf32.f32 "
        "{%0,%1,%2,%3}, {%4,%5,%6,%7}, {%8,%9}, {%0,%1,%2,%3};"
        : "+f"(c[0]), "+f"(c[1]), "+f"(c[2]), "+f"(c[3])
        : "r"(a[0]), "r"(a[1]), "r"(a[2]), "r"(a[3]), "r"(b[0]), "r"(b[1]));
}

__global__ __launch_bounds__(256, 2)
void gemm_tf32(const float* __restrict__ A, const float* __restrict__ Bw,
               const float* __restrict__ bias, const float* __restrict__ resid,
               float* __restrict__ C, int M, int N, int K)
{
    __shared__ uint32_t As[128][36];
    __shared__ uint32_t Bs[32][132];

    const int tid  = threadIdx.x;
    const int lane = tid & 31;
    const int wid  = tid >> 5;
    const int wm   = wid >> 2;
    const int wn   = wid & 3;
    const int g    = lane >> 2;
    const int tg   = lane & 3;
    const int m0   = blockIdx.y * 128;
    const int n0   = blockIdx.x * 128;

    float c[4][4][4];
#pragma unroll
    for (int i = 0; i < 4; i++)
#pragma unroll
        for (int j = 0; j < 4; j++)
#pragma unroll
            for (int r = 0; r < 4; r++) c[i][j][r] = 0.0f;

    const int a_kq = tid & 7;
    const int a_m  = tid >> 3;
    const int b_n4 = tid & 31;
    const int b_k  = tid >> 5;

    for (int k0 = 0; k0 < K; k0 += 32) {
#pragma unroll
        for (int i = 0; i < 4; i++) {
            int m = a_m + 32 * i;
            float4 v = make_float4(0.f, 0.f, 0.f, 0.f);
            if (m0 + m < M) v = *(const float4*)(A + (size_t)(m0 + m) * K + k0 + a_kq * 4);
            uint4 t;
            t.x = f2tf32(v.x); t.y = f2tf32(v.y); t.z = f2tf32(v.z); t.w = f2tf32(v.w);
            *(uint4*)&As[m][a_kq * 4] = t;
        }
#pragma unroll
        for (int i = 0; i < 4; i++) {
            int k = b_k + 8 * i;
            float4 v = *(const float4*)(Bw + (size_t)(k0 + k) * N + n0 + b_n4 * 4);
            uint4 t;
            t.x = f2tf32(v.x); t.y = f2tf32(v.y); t.z = f2tf32(v.z); t.w = f2tf32(v.w);
            *(uint4*)&Bs[k][b_n4 * 4] = t;
        }
        __syncthreads();

#pragma unroll
        for (int kk = 0; kk < 4; kk++) {
            uint32_t a[4][4], b[4][2];
#pragma unroll
            for (int mf = 0; mf < 4; mf++) {
                int m = wm * 64 + mf * 16 + g;
                a[mf][0] = As[m][kk * 8 + tg];
                a[mf][1] = As[m + 8][kk * 8 + tg];
                a[mf][2] = As[m][kk * 8 + tg + 4];
                a[mf][3] = As[m + 8][kk * 8 + tg + 4];
            }
#pragma unroll
            for (int nf = 0; nf < 4; nf++) {
                int n = wn * 32 + nf * 8 + g;
                b[nf][0] = Bs[kk * 8 + tg][n];
                b[nf][1] = Bs[kk * 8 + tg + 4][n];
            }
#pragma unroll
            for (int mf = 0; mf < 4; mf++)
#pragma unroll
                for (int nf = 0; nf < 4; nf++)
                    mma_tf32(c[mf][nf], a[mf], b[nf]);
        }
        __syncthreads();
    }

#pragma unroll
    for (int mf = 0; mf < 4; mf++) {
        const int r0 = m0 + wm * 64 + mf * 16 + g;
        const int r1 = r0 + 8;
#pragma unroll
        for (int nf = 0; nf < 4; nf++) {
            const int cb = n0 + wn * 32 + nf * 8 + 2 * tg;
            const float bx = bias[cb], by = bias[cb + 1];
            if (r0 < M) {
                float2 o = make_float2(c[mf][nf][0] + bx, c[mf][nf][1] + by);
                if (resid) {
                    const float2 rr = *(const float2*)(resid + (size_t)r0 * N + cb);
                    o.x += rr.x; o.y += rr.y;
                }
                *(float2*)(C + (size_t)r0 * N + cb) = o;
            }
            if (r1 < M) {
                float2 o = make_float2(c[mf][nf][2] + bx, c[mf][nf][3] + by);
                if (resid) {
                    const float2 rr = *(const float2*)(resid + (size_t)r1 * N + cb);
                    o.x += rr.x; o.y += rr.y;
                }
                *(float2*)(C + (size_t)r1 * N + cb) = o;
            }
        }
    }
}

// ---------------------------------------------------------------------------
// Fused softmax + deformable sampling — proven; reads concat offlg (stride 384).
// ---------------------------------------------------------------------------
__global__ __launch_bounds__(256, 4)
void msda_sample(const float* __restrict__ offlg, const float* __restrict__ ref,
                 const __half* __restrict__ v, float* __restrict__ mid)
{
    const int lvlH[NLn]     = {92, 46, 23, 12};
    const int lvlW[NLn]     = {160, 80, 40, 20};
    const int lvlStart[NLn] = {0, 14720, 18400, 19320};

    const int row = blockIdx.x;
    const int b   = row / Qn;
    const int t   = threadIdx.x;

    __shared__ float s_loc[256];
    __shared__ float s_lg[128];
    __shared__ int4   s_idx[128];
    __shared__ float4 s_wgt[128];

    const float* __restrict__ rowp = offlg + (size_t)row * 384;

    {
        const int c = t & 1;
        const int l = (t >> 3) & 3;
        const float dim = (c == 0) ? (float)lvlW[l] : (float)lvlH[l];
        const float r = ref[((size_t)row * NLn + l) * 2 + c];
        s_loc[t] = r * dim - 0.5f + rowp[t];
    }
    if (t < 128) s_lg[t] = rowp[256 + t];
    __syncthreads();

    if (t < 128) {
        const int h = t >> 4;
        float m = -1e30f;
#pragma unroll
        for (int i = 0; i < 16; i++) m = fmaxf(m, s_lg[h * 16 + i]);
        float sum = 0.0f;
#pragma unroll
        for (int i = 0; i < 16; i++) sum += __expf(s_lg[h * 16 + i] - m);
        const float w = __expf(s_lg[t] - m) / sum;

        const int l = (t >> 2) & 3;
        const int Hl = lvlH[l], Wl = lvlW[l], base = lvlStart[l];
        const float x = s_loc[t * 2 + 0];
        const float y = s_loc[t * 2 + 1];
        const float xf = floorf(x), yf = floorf(y);
        const float wx = x - xf, wy = y - yf;
        const int x0 = (int)xf, y0 = (int)yf, x1 = x0 + 1, y1 = y0 + 1;

        const bool vx0 = (x0 >= 0) & (x0 < Wl), vx1 = (x1 >= 0) & (x1 < Wl);
        const bool vy0 = (y0 >= 0) & (y0 < Hl), vy1 = (y1 >= 0) & (y1 < Hl);
        const int xc0 = min(max(x0, 0), Wl - 1), xc1 = min(max(x1, 0), Wl - 1);
        const int yc0 = min(max(y0, 0), Hl - 1), yc1 = min(max(y1, 0), Hl - 1);

        int4 id;
        id.x = base + yc0 * Wl + xc0;
        id.y = base + yc0 * Wl + xc1;
        id.z = base + yc1 * Wl + xc0;
        id.w = base + yc1 * Wl + xc1;
        s_idx[t] = id;
        float4 ww;
        ww.x = (vy0 & vx0) ? w * (1.f - wy) * (1.f - wx) : 0.f;
        ww.y = (vy0 & vx1) ? w * (1.f - wy) * wx : 0.f;
        ww.z = (vy1 & vx0) ? w * wy * (1.f - wx) : 0.f;
        ww.w = (vy1 & vx1) ? w * wy * wx : 0.f;
        s_wgt[t] = ww;
    }
    __syncthreads();

    const int h = t >> 5;
    const int d = t & 31;
    const __half* __restrict__ vb = v + (size_t)b * Sn * En + h * HDn + d;

    float acc = 0.0f;
#pragma unroll
    for (int s = 0; s < 16; s++) {
        const int si = h * 16 + s;
        const int4   id = s_idx[si];
        const float4 ww = s_wgt[si];
        acc += ww.x * __half2float(vb[(size_t)id.x * En]);
        acc += ww.y * __half2float(vb[(size_t)id.y * En]);
        acc += ww.z * __half2float(vb[(size_t)id.z * En]);
        acc += ww.w * __half2float(vb[(size_t)id.w * En]);
    }

    mid[(size_t)row * En + t] = acc;
}

// ---------------------------------------------------------------------------
extern "C" void kernel_launch(void* const* d_in, const int* in_sizes, int n_in,
                              void* d_out, int out_size)
{
    const float* query  = (const float*)d_in[0];
    const float* value  = (const float*)d_in[1];
    const float* refpts = (const float*)d_in[2];
    const float* W_off  = (const float*)d_in[4];
    const float* b_off  = (const float*)d_in[5];
    const float* W_attn = (const float*)d_in[6];
    const float* b_attn = (const float*)d_in[7];
    const float* W_v    = (const float*)d_in[8];
    const float* b_v    = (const float*)d_in[9];
    const float* W_out  = (const float*)d_in[10];
    const float* b_out  = (const float*)d_in[11];
    float* out = (float*)d_out;

    void *pvh, *pwt, *polg, *pmid, *pwc, *pbc;
    cudaGetSymbolAddress(&pvh, g_vh);
    cudaGetSymbolAddress(&pwt, g_wt);
    cudaGetSymbolAddress(&polg, g_offlg);
    cudaGetSymbolAddress(&pmid, g_mid);
    cudaGetSymbolAddress(&pwc, g_wc);
    cudaGetSymbolAddress(&pbc, g_bc);
    __half* vh_s = (__half*)pvh;
    __half* wt_s = (__half*)pwt;
    float* olg_s = (float*)polg;
    float* mid_s = (float*)pmid;
    float* wc_s  = (float*)pwc;
    float* bc_s  = (float*)pbc;

    // 0a) transpose + fp16-convert W_v -> Wt[n][k]
    {
        dim3 grid(En / 32, En / 32);
        transpose_w_h<<<grid, dim3(32, 8)>>>(W_v, wt_s);
    }
    // 0b) concat offset/attn weights -> [256,384]
    concat_wb<<<En, 384>>>(W_off, b_off, W_attn, b_attn, wc_s, bc_s);

    // 1) value projection: [156480,256] @ [256,256]  (fp16 MMA, half output)
    {
        dim3 grid(En / 128, (Mv + 127) / 128);
        gemm_f16v<<<grid, 256>>>(value, wt_s, b_v, vh_s, Mv, En, En);
    }
    // 2) combined offset+logit projection: [7200,256] @ [256,384]  (tf32)
    {
        dim3 grid(384 / 128, (BQn + 127) / 128);
        gemm_tf32<<<grid, 256>>>(query, wc_s, bc_s, nullptr, olg_s, BQn, 384, En);
    }
    // 3) softmax + deformable bilinear sampling (fp16 gathers)
    msda_sample<<<BQn, 256>>>(olg_s, refpts, vh_s, mid_s);
    // 4) output projection + residual: [7200,256] @ [256,256] + query  (tf32)
    {
        dim3 grid(En / 128, (BQn + 127) / 128);
        gemm_tf32<<<grid, 256>>>(mid_s, W_out, b_out, query, out, BQn, En, En);
    }
}

// round 12
// speedup vs baseline: 1.6797x; 1.0284x over previous
#include <cuda_runtime.h>
#include <cuda_fp16.h>
#include <cstdint>
#include <cstddef>

// Problem constants
#define Bn   8
#define Qn   900
#define En   256
#define NHn  8
#define HDn  32
#define NLn  4
#define NPn  4
#define Sn   19560
#define BQn  (Bn * Qn)          // 7200
#define Mv   (Bn * Sn)          // 156480

// Scratch (static device globals)
__device__ __half g_vh[(size_t)Bn * Sn * En];    // projected values [B,S,E] fp16
__device__ __half g_wt[(size_t)En * En];         // W_v^T fp16  [n][k]
__device__ float g_offlg[(size_t)BQn * 384];     // [off(256) | logits(128)] per row
__device__ float g_mid[(size_t)BQn * En];
__device__ float g_wc[(size_t)En * 384];         // W_off || W_attn  [k][384]
__device__ float g_bc[384];                      // b_off || b_attn

// ---------------------------------------------------------------------------
// W_v transpose + fp16 convert: Wt[n][k] = half(W[k][n]), 256x256.
// ---------------------------------------------------------------------------
__global__ void transpose_w_h(const float* __restrict__ W, __half* __restrict__ Wt)
{
    __shared__ float tile[32][33];
    const int bx = blockIdx.x * 32;   // n block
    const int by = blockIdx.y * 32;   // k block
    const int tx = threadIdx.x, ty = threadIdx.y;   // 32 x 8
#pragma unroll
    for (int i = 0; i < 32; i += 8)
        tile[ty + i][tx] = W[(size_t)(by + ty + i) * En + bx + tx];
    __syncthreads();
#pragma unroll
    for (int i = 0; i < 32; i += 8)
        Wt[(size_t)(bx + ty + i) * En + by + tx] = __float2half_rn(tile[tx][ty + i]);
}

// ---------------------------------------------------------------------------
// Weight concat (fixed battn index — proven).
// ---------------------------------------------------------------------------
__global__ void concat_wb(const float* __restrict__ Woff, const float* __restrict__ boff,
                          const float* __restrict__ Wattn, const float* __restrict__ battn,
                          float* __restrict__ Wc, float* __restrict__ bc)
{
    const int k = blockIdx.x;
    const int t = threadIdx.x;  // 384
    Wc[(size_t)k * 384 + t] = (t < 256) ? Woff[(size_t)k * 256 + t]
                                        : Wattn[(size_t)k * 128 + (t - 256)];
    if (k == 0) bc[t] = (t < 256) ? boff[t] : battn[t - 256];
}

// ---------------------------------------------------------------------------
// fp16 tensor-core GEMM (m16n8k16) for the value projection — round-8 proven.
// ---------------------------------------------------------------------------
__device__ __forceinline__ void mma_f16(float* c, const uint32_t* a, const uint32_t* b) {
    asm volatile(
        "mma.sync.aligned.m16n8k16.row.col.f32.f16.f16.f32 "
        "{%0,%1,%2,%3}, {%4,%5,%6,%7}, {%8,%9}, {%0,%1,%2,%3};"
        : "+f"(c[0]), "+f"(c[1]), "+f"(c[2]), "+f"(c[3])
        : "r"(a[0]), "r"(a[1]), "r"(a[2]), "r"(a[3]), "r"(b[0]), "r"(b[1]));
}

__global__ __launch_bounds__(256, 2)
void gemm_f16v(const float* __restrict__ A, const __half* __restrict__ Wt,
               const float* __restrict__ bias, __half* __restrict__ C,
               int M, int N, int K)
{
    __shared__ __half As[128][40];
    __shared__ __half Bsn[128][40];

    const int tid  = threadIdx.x;
    const int lane = tid & 31;
    const int wid  = tid >> 5;
    const int wm   = wid >> 2;
    const int wn   = wid & 3;
    const int g    = lane >> 2;
    const int tg   = lane & 3;
    const int m0   = blockIdx.y * 128;
    const int n0   = blockIdx.x * 128;

    float c[4][4][4];
#pragma unroll
    for (int i = 0; i < 4; i++)
#pragma unroll
        for (int j = 0; j < 4; j++)
#pragma unroll
            for (int r = 0; r < 4; r++) c[i][j][r] = 0.0f;

    const int a_kq = tid & 7;
    const int a_m  = tid >> 3;
    const int b_nr = tid >> 2;
    const int b_q  = tid & 3;

    for (int k0 = 0; k0 < K; k0 += 32) {
#pragma unroll
        for (int i = 0; i < 4; i++) {
            int m = a_m + 32 * i;
            float4 v = make_float4(0.f, 0.f, 0.f, 0.f);
            if (m0 + m < M) v = *(const float4*)(A + (size_t)(m0 + m) * K + k0 + a_kq * 4);
            __half2 h01 = __floats2half2_rn(v.x, v.y);
            __half2 h23 = __floats2half2_rn(v.z, v.w);
            uint2 pk;
            pk.x = *(uint32_t*)&h01;
            pk.y = *(uint32_t*)&h23;
            *(uint2*)&As[m][a_kq * 4] = pk;
        }
#pragma unroll
        for (int i = 0; i < 2; i++) {
            int n = b_nr + 64 * i;
            uint4 v = *(const uint4*)(Wt + (size_t)(n0 + n) * K + k0 + b_q * 8);
            *(uint4*)&Bsn[n][b_q * 8] = v;
        }
        __syncthreads();

#pragma unroll
        for (int kk = 0; kk < 2; kk++) {
            uint32_t a[4][4], b[4][2];
#pragma unroll
            for (int mf = 0; mf < 4; mf++) {
                int m = wm * 64 + mf * 16 + g;
                a[mf][0] = *(const uint32_t*)&As[m][kk * 16 + 2 * tg];
                a[mf][1] = *(const uint32_t*)&As[m + 8][kk * 16 + 2 * tg];
                a[mf][2] = *(const uint32_t*)&As[m][kk * 16 + 2 * tg + 8];
                a[mf][3] = *(const uint32_t*)&As[m + 8][kk * 16 + 2 * tg + 8];
            }
#pragma unroll
            for (int nf = 0; nf < 4; nf++) {
                int n = wn * 32 + nf * 8 + g;
                b[nf][0] = *(const uint32_t*)&Bsn[n][kk * 16 + 2 * tg];
                b[nf][1] = *(const uint32_t*)&Bsn[n][kk * 16 + 2 * tg + 8];
            }
#pragma unroll
            for (int mf = 0; mf < 4; mf++)
#pragma unroll
                for (int nf = 0; nf < 4; nf++)
                    mma_f16(c[mf][nf], a[mf], b[nf]);
        }
        __syncthreads();
    }

#pragma unroll
    for (int mf = 0; mf < 4; mf++) {
        const int r0 = m0 + wm * 64 + mf * 16 + g;
        const int r1 = r0 + 8;
#pragma unroll
        for (int nf = 0; nf < 4; nf++) {
            const int cb = n0 + wn * 32 + nf * 8 + 2 * tg;
            const float bx = bias[cb], by = bias[cb + 1];
            if (r0 < M) {
                __half2 o = __floats2half2_rn(c[mf][nf][0] + bx, c[mf][nf][1] + by);
                *(__half2*)(C + (size_t)r0 * N + cb) = o;
            }
            if (r1 < M) {
                __half2 o = __floats2half2_rn(c[mf][nf][2] + bx, c[mf][nf][3] + by);
                *(__half2*)(C + (size_t)r1 * N + cb) = o;
            }
        }
    }
}

// ---------------------------------------------------------------------------
// tf32 tensor-core GEMM, cp.async double-buffered (round-4 structure, now
// exonerated — its failure was the concat OOB, not this kernel).
// Regs stay ~128 (no register-file transit for staged tiles).
// ---------------------------------------------------------------------------
__device__ __forceinline__ uint32_t f2tf32(float f) {
    uint32_t r;
    asm("cvt.rna.tf32.f32 %0, %1;" : "=r"(r) : "f"(f));
    return r;
}

__device__ __forceinline__ void mma_tf32(float* c, const uint32_t* a, const uint32_t* b) {
    asm volatile(
        "mma.sync.aligned.m16n8k8.row.col.f32.tf32.tf32.f32 "
        "{%0,%1,%2,%3}, {%4,%5,%6,%7}, {%8,%9}, {%0,%1,%2,%3};"
        : "+f"(c[0]), "+f"(c[1]), "+f"(c[2]), "+f"(c[3])
        : "r"(a[0]), "r"(a[1]), "r"(a[2]), "r"(a[3]), "r"(b[0]), "r"(b[1]));
}

__device__ __forceinline__ void cp_async16(void* smem_dst, const void* gsrc, int src_bytes) {
    uint32_t d = (uint32_t)__cvta_generic_to_shared(smem_dst);
    asm volatile("cp.async.cg.shared.global [%0], [%1], 16, %2;"
                 :: "r"(d), "l"(gsrc), "r"(src_bytes) : "memory");
}
#define CP_ASYNC_COMMIT() asm volatile("cp.async.commit_group;" ::: "memory")
#define CP_ASYNC_WAIT1()  asm volatile("cp.async.wait_group 1;" ::: "memory")
#define CP_ASYNC_WAIT0()  asm volatile("cp.async.wait_group 0;" ::: "memory")

__global__ __launch_bounds__(256, 2)
void gemm_tf32(const float* __restrict__ A, const float* __restrict__ Bw,
               const float* __restrict__ bias, const float* __restrict__ resid,
               float* __restrict__ C, int M, int N, int K)
{
    __shared__ float As[2][128][36];
    __shared__ float Bs[2][32][132];

    const int tid  = threadIdx.x;
    const int lane = tid & 31;
    const int wid  = tid >> 5;
    const int wm   = wid >> 2;
    const int wn   = wid & 3;
    const int g    = lane >> 2;
    const int tg   = lane & 3;
    const int m0   = blockIdx.y * 128;
    const int n0   = blockIdx.x * 128;

    float c[4][4][4];
#pragma unroll
    for (int i = 0; i < 4; i++)
#pragma unroll
        for (int j = 0; j < 4; j++)
#pragma unroll
            for (int r = 0; r < 4; r++) c[i][j][r] = 0.0f;

    const int a_kq = tid & 7;
    const int a_m  = tid >> 3;
    const int b_n4 = tid & 31;
    const int b_k  = tid >> 5;

    const int NC = K / 32;

    auto load_chunk = [&](int k0, int buf) {
#pragma unroll
        for (int i = 0; i < 4; i++) {
            int m = a_m + 32 * i;
            int gm = m0 + m;
            int ok = (gm < M) ? 16 : 0;
            int gmc = (gm < M) ? gm : 0;
            cp_async16(&As[buf][m][a_kq * 4], A + (size_t)gmc * K + k0 + a_kq * 4, ok);
        }
#pragma unroll
        for (int i = 0; i < 4; i++) {
            int k = b_k + 8 * i;
            cp_async16(&Bs[buf][k][b_n4 * 4], Bw + (size_t)(k0 + k) * N + n0 + b_n4 * 4, 16);
        }
        CP_ASYNC_COMMIT();
    };

    load_chunk(0, 0);

    for (int cidx = 0; cidx < NC; cidx++) {
        const int buf = cidx & 1;
        if (cidx + 1 < NC) {
            load_chunk((cidx + 1) * 32, (cidx + 1) & 1);
            CP_ASYNC_WAIT1();
        } else {
            CP_ASYNC_WAIT0();
        }
        __syncthreads();

#pragma unroll
        for (int kk = 0; kk < 4; kk++) {
            uint32_t a[4][4], b[4][2];
#pragma unroll
            for (int mf = 0; mf < 4; mf++) {
                int m = wm * 64 + mf * 16 + g;
                a[mf][0] = f2tf32(As[buf][m][kk * 8 + tg]);
                a[mf][1] = f2tf32(As[buf][m + 8][kk * 8 + tg]);
                a[mf][2] = f2tf32(As[buf][m][kk * 8 + tg + 4]);
                a[mf][3] = f2tf32(As[buf][m + 8][kk * 8 + tg + 4]);
            }
#pragma unroll
            for (int nf = 0; nf < 4; nf++) {
                int n = wn * 32 + nf * 8 + g;
                b[nf][0] = f2tf32(Bs[buf][kk * 8 + tg][n]);
                b[nf][1] = f2tf32(Bs[buf][kk * 8 + tg + 4][n]);
            }
#pragma unroll
            for (int mf = 0; mf < 4; mf++)
#pragma unroll
                for (int nf = 0; nf < 4; nf++)
                    mma_tf32(c[mf][nf], a[mf], b[nf]);
        }
        __syncthreads();
    }

#pragma unroll
    for (int mf = 0; mf < 4; mf++) {
        const int r0 = m0 + wm * 64 + mf * 16 + g;
        const int r1 = r0 + 8;
#pragma unroll
        for (int nf = 0; nf < 4; nf++) {
            const int cb = n0 + wn * 32 + nf * 8 + 2 * tg;
            const float bx = bias[cb], by = bias[cb + 1];
            if (r0 < M) {
                float2 o = make_float2(c[mf][nf][0] + bx, c[mf][nf][1] + by);
                if (resid) {
                    const float2 rr = *(const float2*)(resid + (size_t)r0 * N + cb);
                    o.x += rr.x; o.y += rr.y;
                }
                *(float2*)(C + (size_t)r0 * N + cb) = o;
            }
            if (r1 < M) {
                float2 o = make_float2(c[mf][nf][2] + bx, c[mf][nf][3] + by);
                if (resid) {
                    const float2 rr = *(const float2*)(resid + (size_t)r1 * N + cb);
                    o.x += rr.x; o.y += rr.y;
                }
                *(float2*)(C + (size_t)r1 * N + cb) = o;
            }
        }
    }
}

// ---------------------------------------------------------------------------
// Fused softmax + deformable sampling — proven structure; occupancy raised
// to 6 CTAs/SM (regs capped ~42) to hide gather latency.
// ---------------------------------------------------------------------------
__global__ __launch_bounds__(256, 6)
void msda_sample(const float* __restrict__ offlg, const float* __restrict__ ref,
                 const __half* __restrict__ v, float* __restrict__ mid)
{
    const int lvlH[NLn]     = {92, 46, 23, 12};
    const int lvlW[NLn]     = {160, 80, 40, 20};
    const int lvlStart[NLn] = {0, 14720, 18400, 19320};

    const int row = blockIdx.x;
    const int b   = row / Qn;
    const int t   = threadIdx.x;

    __shared__ float s_loc[256];
    __shared__ float s_lg[128];
    __shared__ int4   s_idx[128];
    __shared__ float4 s_wgt[128];

    const float* __restrict__ rowp = offlg + (size_t)row * 384;

    {
        const int c = t & 1;
        const int l = (t >> 3) & 3;
        const float dim = (c == 0) ? (float)lvlW[l] : (float)lvlH[l];
        const float r = ref[((size_t)row * NLn + l) * 2 + c];
        s_loc[t] = r * dim - 0.5f + rowp[t];
    }
    if (t < 128) s_lg[t] = rowp[256 + t];
    __syncthreads();

    if (t < 128) {
        const int h = t >> 4;
        float m = -1e30f;
#pragma unroll
        for (int i = 0; i < 16; i++) m = fmaxf(m, s_lg[h * 16 + i]);
        float sum = 0.0f;
#pragma unroll
        for (int i = 0; i < 16; i++) sum += __expf(s_lg[h * 16 + i] - m);
        const float w = __expf(s_lg[t] - m) / sum;

        const int l = (t >> 2) & 3;
        const int Hl = lvlH[l], Wl = lvlW[l], base = lvlStart[l];
        const float x = s_loc[t * 2 + 0];
        const float y = s_loc[t * 2 + 1];
        const float xf = floorf(x), yf = floorf(y);
        const float wx = x - xf, wy = y - yf;
        const int x0 = (int)xf, y0 = (int)yf, x1 = x0 + 1, y1 = y0 + 1;

        const bool vx0 = (x0 >= 0) & (x0 < Wl), vx1 = (x1 >= 0) & (x1 < Wl);
        const bool vy0 = (y0 >= 0) & (y0 < Hl), vy1 = (y1 >= 0) & (y1 < Hl);
        const int xc0 = min(max(x0, 0), Wl - 1), xc1 = min(max(x1, 0), Wl - 1);
        const int yc0 = min(max(y0, 0), Hl - 1), yc1 = min(max(y1, 0), Hl - 1);

        int4 id;
        id.x = base + yc0 * Wl + xc0;
        id.y = base + yc0 * Wl + xc1;
        id.z = base + yc1 * Wl + xc0;
        id.w = base + yc1 * Wl + xc1;
        s_idx[t] = id;
        float4 ww;
        ww.x = (vy0 & vx0) ? w * (1.f - wy) * (1.f - wx) : 0.f;
        ww.y = (vy0 & vx1) ? w * (1.f - wy) * wx : 0.f;
        ww.z = (vy1 & vx0) ? w * wy * (1.f - wx) : 0.f;
        ww.w = (vy1 & vx1) ? w * wy * wx : 0.f;
        s_wgt[t] = ww;
    }
    __syncthreads();

    const int h = t >> 5;
    const int d = t & 31;
    const __half* __restrict__ vb = v + (size_t)b * Sn * En + h * HDn + d;

    float acc = 0.0f;
#pragma unroll
    for (int s = 0; s < 16; s++) {
        const int si = h * 16 + s;
        const int4   id = s_idx[si];
        const float4 ww = s_wgt[si];
        acc += ww.x * __half2float(vb[(size_t)id.x * En]);
        acc += ww.y * __half2float(vb[(size_t)id.y * En]);
        acc += ww.z * __half2float(vb[(size_t)id.z * En]);
        acc += ww.w * __half2float(vb[(size_t)id.w * En]);
    }

    mid[(size_t)row * En + t] = acc;
}

// ---------------------------------------------------------------------------
extern "C" void kernel_launch(void* const* d_in, const int* in_sizes, int n_in,
                              void* d_out, int out_size)
{
    const float* query  = (const float*)d_in[0];
    const float* value  = (const float*)d_in[1];
    const float* refpts = (const float*)d_in[2];
    const float* W_off  = (const float*)d_in[4];
    const float* b_off  = (const float*)d_in[5];
    const float* W_attn = (const float*)d_in[6];
    const float* b_attn = (const float*)d_in[7];
    const float* W_v    = (const float*)d_in[8];
    const float* b_v    = (const float*)d_in[9];
    const float* W_out  = (const float*)d_in[10];
    const float* b_out  = (const float*)d_in[11];
    float* out = (float*)d_out;

    void *pvh, *pwt, *polg, *pmid, *pwc, *pbc;
    cudaGetSymbolAddress(&pvh, g_vh);
    cudaGetSymbolAddress(&pwt, g_wt);
    cudaGetSymbolAddress(&polg, g_offlg);
    cudaGetSymbolAddress(&pmid, g_mid);
    cudaGetSymbolAddress(&pwc, g_wc);
    cudaGetSymbolAddress(&pbc, g_bc);
    __half* vh_s = (__half*)pvh;
    __half* wt_s = (__half*)pwt;
    float* olg_s = (float*)polg;
    float* mid_s = (float*)pmid;
    float* wc_s  = (float*)pwc;
    float* bc_s  = (float*)pbc;

    // 0a) transpose + fp16-convert W_v -> Wt[n][k]
    {
        dim3 grid(En / 32, En / 32);
        transpose_w_h<<<grid, dim3(32, 8)>>>(W_v, wt_s);
    }
    // 0b) concat offset/attn weights -> [256,384]
    concat_wb<<<En, 384>>>(W_off, b_off, W_attn, b_attn, wc_s, bc_s);

    // 1) value projection: [156480,256] @ [256,256]  (fp16 MMA, half output)
    {
        dim3 grid(En / 128, (Mv + 127) / 128);
        gemm_f16v<<<grid, 256>>>(value, wt_s, b_v, vh_s, Mv, En, En);
    }
    // 2) combined offset+logit projection: [7200,256] @ [256,384]  (tf32, cp.async)
    {
        dim3 grid(384 / 128, (BQn + 127) / 128);
        gemm_tf32<<<grid, 256>>>(query, wc_s, bc_s, nullptr, olg_s, BQn, 384, En);
    }
    // 3) softmax + deformable bilinear sampling (fp16 gathers, occ 6)
    msda_sample<<<BQn, 256>>>(olg_s, refpts, vh_s, mid_s);
    // 4) output projection + residual: [7200,256] @ [256,256] + query  (tf32, cp.async)
    {
        dim3 grid(En / 128, (BQn + 127) / 128);
        gemm_tf32<<<grid, 256>>>(mid_s, W_out, b_out, query, out, BQn, En, En);
    }
}

// round 13
// speedup vs baseline: 1.8040x; 1.0740x over previous
#include <cuda_runtime.h>
#include <cuda_fp16.h>
#include <cstdint>
#include <cstddef>

// Problem constants
#define Bn   8
#define Qn   900
#define En   256
#define NHn  8
#define HDn  32
#define NLn  4
#define NPn  4
#define Sn   19560
#define BQn  (Bn * Qn)          // 7200
#define Mv   (Bn * Sn)          // 156480

// Scratch (static device globals)
__device__ __half g_vh[(size_t)Bn * Sn * En];    // projected values [B,S,E] fp16
__device__ __half g_wt[(size_t)En * En];         // W_v^T fp16  [n][k]
__device__ float g_offlg[(size_t)BQn * 384];     // [off(256) | logits(128)] per row
__device__ float g_mid[(size_t)BQn * En];
__device__ float g_wc[(size_t)En * 384];         // W_off || W_attn  [k][384]
__device__ float g_bc[384];                      // b_off || b_attn

// ---------------------------------------------------------------------------
// W_v transpose + fp16 convert: Wt[n][k] = half(W[k][n]), 256x256.
// ---------------------------------------------------------------------------
__global__ void transpose_w_h(const float* __restrict__ W, __half* __restrict__ Wt)
{
    __shared__ float tile[32][33];
    const int bx = blockIdx.x * 32;   // n block
    const int by = blockIdx.y * 32;   // k block
    const int tx = threadIdx.x, ty = threadIdx.y;   // 32 x 8
#pragma unroll
    for (int i = 0; i < 32; i += 8)
        tile[ty + i][tx] = W[(size_t)(by + ty + i) * En + bx + tx];
    __syncthreads();
#pragma unroll
    for (int i = 0; i < 32; i += 8)
        Wt[(size_t)(bx + ty + i) * En + by + tx] = __float2half_rn(tile[tx][ty + i]);
}

// ---------------------------------------------------------------------------
// Weight concat (fixed battn index — proven).
// ---------------------------------------------------------------------------
__global__ void concat_wb(const float* __restrict__ Woff, const float* __restrict__ boff,
                          const float* __restrict__ Wattn, const float* __restrict__ battn,
                          float* __restrict__ Wc, float* __restrict__ bc)
{
    const int k = blockIdx.x;
    const int t = threadIdx.x;  // 384
    Wc[(size_t)k * 384 + t] = (t < 256) ? Woff[(size_t)k * 256 + t]
                                        : Wattn[(size_t)k * 128 + (t - 256)];
    if (k == 0) bc[t] = (t < 256) ? boff[t] : battn[t - 256];
}

// ---------------------------------------------------------------------------
// fp16 tensor-core GEMM (m16n8k16) for the value projection — round-8 proven.
// ---------------------------------------------------------------------------
__device__ __forceinline__ void mma_f16(float* c, const uint32_t* a, const uint32_t* b) {
    asm volatile(
        "mma.sync.aligned.m16n8k16.row.col.f32.f16.f16.f32 "
        "{%0,%1,%2,%3}, {%4,%5,%6,%7}, {%8,%9}, {%0,%1,%2,%3};"
        : "+f"(c[0]), "+f"(c[1]), "+f"(c[2]), "+f"(c[3])
        : "r"(a[0]), "r"(a[1]), "r"(a[2]), "r"(a[3]), "r"(b[0]), "r"(b[1]));
}

__global__ __launch_bounds__(256, 2)
void gemm_f16v(const float* __restrict__ A, const __half* __restrict__ Wt,
               const float* __restrict__ bias, __half* __restrict__ C,
               int M, int N, int K)
{
    __shared__ __half As[128][40];
    __shared__ __half Bsn[128][40];

    const int tid  = threadIdx.x;
    const int lane = tid & 31;
    const int wid  = tid >> 5;
    const int wm   = wid >> 2;
    const int wn   = wid & 3;
    const int g    = lane >> 2;
    const int tg   = lane & 3;
    const int m0   = blockIdx.y * 128;
    const int n0   = blockIdx.x * 128;

    float c[4][4][4];
#pragma unroll
    for (int i = 0; i < 4; i++)
#pragma unroll
        for (int j = 0; j < 4; j++)
#pragma unroll
            for (int r = 0; r < 4; r++) c[i][j][r] = 0.0f;

    const int a_kq = tid & 7;
    const int a_m  = tid >> 3;
    const int b_nr = tid >> 2;
    const int b_q  = tid & 3;

    for (int k0 = 0; k0 < K; k0 += 32) {
#pragma unroll
        for (int i = 0; i < 4; i++) {
            int m = a_m + 32 * i;
            float4 v = make_float4(0.f, 0.f, 0.f, 0.f);
            if (m0 + m < M) v = *(const float4*)(A + (size_t)(m0 + m) * K + k0 + a_kq * 4);
            __half2 h01 = __floats2half2_rn(v.x, v.y);
            __half2 h23 = __floats2half2_rn(v.z, v.w);
            uint2 pk;
            pk.x = *(uint32_t*)&h01;
            pk.y = *(uint32_t*)&h23;
            *(uint2*)&As[m][a_kq * 4] = pk;
        }
#pragma unroll
        for (int i = 0; i < 2; i++) {
            int n = b_nr + 64 * i;
            uint4 v = *(const uint4*)(Wt + (size_t)(n0 + n) * K + k0 + b_q * 8);
            *(uint4*)&Bsn[n][b_q * 8] = v;
        }
        __syncthreads();

#pragma unroll
        for (int kk = 0; kk < 2; kk++) {
            uint32_t a[4][4], b[4][2];
#pragma unroll
            for (int mf = 0; mf < 4; mf++) {
                int m = wm * 64 + mf * 16 + g;
                a[mf][0] = *(const uint32_t*)&As[m][kk * 16 + 2 * tg];
                a[mf][1] = *(const uint32_t*)&As[m + 8][kk * 16 + 2 * tg];
                a[mf][2] = *(const uint32_t*)&As[m][kk * 16 + 2 * tg + 8];
                a[mf][3] = *(const uint32_t*)&As[m + 8][kk * 16 + 2 * tg + 8];
            }
#pragma unroll
            for (int nf = 0; nf < 4; nf++) {
                int n = wn * 32 + nf * 8 + g;
                b[nf][0] = *(const uint32_t*)&Bsn[n][kk * 16 + 2 * tg];
                b[nf][1] = *(const uint32_t*)&Bsn[n][kk * 16 + 2 * tg + 8];
            }
#pragma unroll
            for (int mf = 0; mf < 4; mf++)
#pragma unroll
                for (int nf = 0; nf < 4; nf++)
                    mma_f16(c[mf][nf], a[mf], b[nf]);
        }
        __syncthreads();
    }

#pragma unroll
    for (int mf = 0; mf < 4; mf++) {
        const int r0 = m0 + wm * 64 + mf * 16 + g;
        const int r1 = r0 + 8;
#pragma unroll
        for (int nf = 0; nf < 4; nf++) {
            const int cb = n0 + wn * 32 + nf * 8 + 2 * tg;
            const float bx = bias[cb], by = bias[cb + 1];
            if (r0 < M) {
                __half2 o = __floats2half2_rn(c[mf][nf][0] + bx, c[mf][nf][1] + by);
                *(__half2*)(C + (size_t)r0 * N + cb) = o;
            }
            if (r1 < M) {
                __half2 o = __floats2half2_rn(c[mf][nf][2] + bx, c[mf][nf][3] + by);
                *(__half2*)(C + (size_t)r1 * N + cb) = o;
            }
        }
    }
}

// ---------------------------------------------------------------------------
// tf32 tensor-core GEMM, cp.async double-buffered, BM=64 tiles (parallelism
// fix: grid 171->339 / 114->226, 2-3 CTAs/SM). Warp tile 32x32.
// Per-output K order identical to prior rounds -> bit-identical numerics.
// ---------------------------------------------------------------------------
__device__ __forceinline__ uint32_t f2tf32(float f) {
    uint32_t r;
    asm("cvt.rna.tf32.f32 %0, %1;" : "=r"(r) : "f"(f));
    return r;
}

__device__ __forceinline__ void mma_tf32(float* c, const uint32_t* a, const uint32_t* b) {
    asm volatile(
        "mma.sync.aligned.m16n8k8.row.col.f32.tf32.tf32.f32 "
        "{%0,%1,%2,%3}, {%4,%5,%6,%7}, {%8,%9}, {%0,%1,%2,%3};"
        : "+f"(c[0]), "+f"(c[1]), "+f"(c[2]), "+f"(c[3])
        : "r"(a[0]), "r"(a[1]), "r"(a[2]), "r"(a[3]), "r"(b[0]), "r"(b[1]));
}

__device__ __forceinline__ void cp_async16(void* smem_dst, const void* gsrc, int src_bytes) {
    uint32_t d = (uint32_t)__cvta_generic_to_shared(smem_dst);
    asm volatile("cp.async.cg.shared.global [%0], [%1], 16, %2;"
                 :: "r"(d), "l"(gsrc), "r"(src_bytes) : "memory");
}
#define CP_ASYNC_COMMIT() asm volatile("cp.async.commit_group;" ::: "memory")
#define CP_ASYNC_WAIT1()  asm volatile("cp.async.wait_group 1;" ::: "memory")
#define CP_ASYNC_WAIT0()  asm volatile("cp.async.wait_group 0;" ::: "memory")

__global__ __launch_bounds__(256, 3)
void gemm_tf32(const float* __restrict__ A, const float* __restrict__ Bw,
               const float* __restrict__ bias, const float* __restrict__ resid,
               float* __restrict__ C, int M, int N, int K)
{
    __shared__ float As[2][64][36];
    __shared__ float Bs[2][32][132];

    const int tid  = threadIdx.x;
    const int lane = tid & 31;
    const int wid  = tid >> 5;
    const int wm   = wid >> 2;          // 0..1
    const int wn   = wid & 3;           // 0..3
    const int g    = lane >> 2;
    const int tg   = lane & 3;
    const int m0   = blockIdx.y * 64;
    const int n0   = blockIdx.x * 128;

    float c[2][4][4];
#pragma unroll
    for (int i = 0; i < 2; i++)
#pragma unroll
        for (int j = 0; j < 4; j++)
#pragma unroll
            for (int r = 0; r < 4; r++) c[i][j][r] = 0.0f;

    const int a_kq = tid & 7;           // float4 col in K-chunk
    const int a_m  = tid >> 3;          // 0..31
    const int b_n4 = tid & 31;
    const int b_k  = tid >> 5;

    const int NC = K / 32;

    auto load_chunk = [&](int k0, int buf) {
#pragma unroll
        for (int i = 0; i < 2; i++) {
            int m = a_m + 32 * i;
            int gm = m0 + m;
            int ok = (gm < M) ? 16 : 0;
            int gmc = (gm < M) ? gm : 0;
            cp_async16(&As[buf][m][a_kq * 4], A + (size_t)gmc * K + k0 + a_kq * 4, ok);
        }
#pragma unroll
        for (int i = 0; i < 4; i++) {
            int k = b_k + 8 * i;
            cp_async16(&Bs[buf][k][b_n4 * 4], Bw + (size_t)(k0 + k) * N + n0 + b_n4 * 4, 16);
        }
        CP_ASYNC_COMMIT();
    };

    load_chunk(0, 0);

    for (int cidx = 0; cidx < NC; cidx++) {
        const int buf = cidx & 1;
        if (cidx + 1 < NC) {
            load_chunk((cidx + 1) * 32, (cidx + 1) & 1);
            CP_ASYNC_WAIT1();
        } else {
            CP_ASYNC_WAIT0();
        }
        __syncthreads();

#pragma unroll
        for (int kk = 0; kk < 4; kk++) {
            uint32_t a[2][4], b[4][2];
#pragma unroll
            for (int mf = 0; mf < 2; mf++) {
                int m = wm * 32 + mf * 16 + g;
                a[mf][0] = f2tf32(As[buf][m][kk * 8 + tg]);
                a[mf][1] = f2tf32(As[buf][m + 8][kk * 8 + tg]);
                a[mf][2] = f2tf32(As[buf][m][kk * 8 + tg + 4]);
                a[mf][3] = f2tf32(As[buf][m + 8][kk * 8 + tg + 4]);
            }
#pragma unroll
            for (int nf = 0; nf < 4; nf++) {
                int n = wn * 32 + nf * 8 + g;
                b[nf][0] = f2tf32(Bs[buf][kk * 8 + tg][n]);
                b[nf][1] = f2tf32(Bs[buf][kk * 8 + tg + 4][n]);
            }
#pragma unroll
            for (int mf = 0; mf < 2; mf++)
#pragma unroll
                for (int nf = 0; nf < 4; nf++)
                    mma_tf32(c[mf][nf], a[mf], b[nf]);
        }
        __syncthreads();
    }

#pragma unroll
    for (int mf = 0; mf < 2; mf++) {
        const int r0 = m0 + wm * 32 + mf * 16 + g;
        const int r1 = r0 + 8;
#pragma unroll
        for (int nf = 0; nf < 4; nf++) {
            const int cb = n0 + wn * 32 + nf * 8 + 2 * tg;
            const float bx = bias[cb], by = bias[cb + 1];
            if (r0 < M) {
                float2 o = make_float2(c[mf][nf][0] + bx, c[mf][nf][1] + by);
                if (resid) {
                    const float2 rr = *(const float2*)(resid + (size_t)r0 * N + cb);
                    o.x += rr.x; o.y += rr.y;
                }
                *(float2*)(C + (size_t)r0 * N + cb) = o;
            }
            if (r1 < M) {
                float2 o = make_float2(c[mf][nf][2] + bx, c[mf][nf][3] + by);
                if (resid) {
                    const float2 rr = *(const float2*)(resid + (size_t)r1 * N + cb);
                    o.x += rr.x; o.y += rr.y;
                }
                *(float2*)(C + (size_t)r1 * N + cb) = o;
            }
        }
    }
}

// ---------------------------------------------------------------------------
// Fused softmax + deformable sampling — half2-vectorized: 128 threads/block,
// each thread owns a channel PAIR (h = t/16, d = 2*(t&15)). Halves LDG count
// at identical sector traffic; all threads active in precompute.
// ---------------------------------------------------------------------------
__global__ __launch_bounds__(128, 12)
void msda_sample(const float* __restrict__ offlg, const float* __restrict__ ref,
                 const __half* __restrict__ v, float* __restrict__ mid)
{
    const int lvlH[NLn]     = {92, 46, 23, 12};
    const int lvlW[NLn]     = {160, 80, 40, 20};
    const int lvlStart[NLn] = {0, 14720, 18400, 19320};

    const int row = blockIdx.x;
    const int b   = row / Qn;
    const int t   = threadIdx.x;   // 0..127

    __shared__ float s_loc[256];
    __shared__ float s_lg[128];
    __shared__ int4   s_idx[128];
    __shared__ float4 s_wgt[128];

    const float* __restrict__ rowp = offlg + (size_t)row * 384;

    // two loc entries per thread
#pragma unroll
    for (int i = 0; i < 2; i++) {
        const int idx = t + i * 128;
        const int c = idx & 1;
        const int l = (idx >> 3) & 3;
        const float dim = (c == 0) ? (float)lvlW[l] : (float)lvlH[l];
        const float r = ref[((size_t)row * NLn + l) * 2 + c];
        s_loc[idx] = r * dim - 0.5f + rowp[idx];
    }
    s_lg[t] = rowp[256 + t];
    __syncthreads();

    // softmax + per-sample corner indices/weights (all 128 threads; sample id = t)
    {
        const int h = t >> 4;
        float m = -1e30f;
#pragma unroll
        for (int i = 0; i < 16; i++) m = fmaxf(m, s_lg[h * 16 + i]);
        float sum = 0.0f;
#pragma unroll
        for (int i = 0; i < 16; i++) sum += __expf(s_lg[h * 16 + i] - m);
        const float w = __expf(s_lg[t] - m) / sum;

        const int l = (t >> 2) & 3;
        const int Hl = lvlH[l], Wl = lvlW[l], base = lvlStart[l];
        const float x = s_loc[t * 2 + 0];
        const float y = s_loc[t * 2 + 1];
        const float xf = floorf(x), yf = floorf(y);
        const float wx = x - xf, wy = y - yf;
        const int x0 = (int)xf, y0 = (int)yf, x1 = x0 + 1, y1 = y0 + 1;

        const bool vx0 = (x0 >= 0) & (x0 < Wl), vx1 = (x1 >= 0) & (x1 < Wl);
        const bool vy0 = (y0 >= 0) & (y0 < Hl), vy1 = (y1 >= 0) & (y1 < Hl);
        const int xc0 = min(max(x0, 0), Wl - 1), xc1 = min(max(x1, 0), Wl - 1);
        const int yc0 = min(max(y0, 0), Hl - 1), yc1 = min(max(y1, 0), Hl - 1);

        int4 id;
        id.x = base + yc0 * Wl + xc0;
        id.y = base + yc0 * Wl + xc1;
        id.z = base + yc1 * Wl + xc0;
        id.w = base + yc1 * Wl + xc1;
        s_idx[t] = id;
        float4 ww;
        ww.x = (vy0 & vx0) ? w * (1.f - wy) * (1.f - wx) : 0.f;
        ww.y = (vy0 & vx1) ? w * (1.f - wy) * wx : 0.f;
        ww.z = (vy1 & vx0) ? w * wy * (1.f - wx) : 0.f;
        ww.w = (vy1 & vx1) ? w * wy * wx : 0.f;
        s_wgt[t] = ww;
    }
    __syncthreads();

    const int h  = t >> 4;          // 0..7
    const int dp = t & 15;          // channel pair 0..15
    const __half* __restrict__ vb = v + (size_t)b * Sn * En + h * HDn + dp * 2;

    float accx = 0.0f, accy = 0.0f;
#pragma unroll
    for (int s = 0; s < 16; s++) {
        const int si = h * 16 + s;
        const int4   id = s_idx[si];
        const float4 ww = s_wgt[si];
        float2 f0 = __half22float2(*(const __half2*)(vb + (size_t)id.x * En));
        float2 f1 = __half22float2(*(const __half2*)(vb + (size_t)id.y * En));
        float2 f2 = __half22float2(*(const __half2*)(vb + (size_t)id.z * En));
        float2 f3 = __half22float2(*(const __half2*)(vb + (size_t)id.w * En));
        accx += ww.x * f0.x + ww.y * f1.x + ww.z * f2.x + ww.w * f3.x;
        accy += ww.x * f0.y + ww.y * f1.y + ww.z * f2.y + ww.w * f3.y;
    }

    *(float2*)(mid + (size_t)row * En + h * HDn + dp * 2) = make_float2(accx, accy);
}

// ---------------------------------------------------------------------------
extern "C" void kernel_launch(void* const* d_in, const int* in_sizes, int n_in,
                              void* d_out, int out_size)
{
    const float* query  = (const float*)d_in[0];
    const float* value  = (const float*)d_in[1];
    const float* refpts = (const float*)d_in[2];
    const float* W_off  = (const float*)d_in[4];
    const float* b_off  = (const float*)d_in[5];
    const float* W_attn = (const float*)d_in[6];
    const float* b_attn = (const float*)d_in[7];
    const float* W_v    = (const float*)d_in[8];
    const float* b_v    = (const float*)d_in[9];
    const float* W_out  = (const float*)d_in[10];
    const float* b_out  = (const float*)d_in[11];
    float* out = (float*)d_out;

    void *pvh, *pwt, *polg, *pmid, *pwc, *pbc;
    cudaGetSymbolAddress(&pvh, g_vh);
    cudaGetSymbolAddress(&pwt, g_wt);
    cudaGetSymbolAddress(&polg, g_offlg);
    cudaGetSymbolAddress(&pmid, g_mid);
    cudaGetSymbolAddress(&pwc, g_wc);
    cudaGetSymbolAddress(&pbc, g_bc);
    __half* vh_s = (__half*)pvh;
    __half* wt_s = (__half*)pwt;
    float* olg_s = (float*)polg;
    float* mid_s = (float*)pmid;
    float* wc_s  = (float*)pwc;
    float* bc_s  = (float*)pbc;

    // 0a) transpose + fp16-convert W_v -> Wt[n][k]
    {
        dim3 grid(En / 32, En / 32);
        transpose_w_h<<<grid, dim3(32, 8)>>>(W_v, wt_s);
    }
    // 0b) concat offset/attn weights -> [256,384]
    concat_wb<<<En, 384>>>(W_off, b_off, W_attn, b_attn, wc_s, bc_s);

    // 1) value projection: [156480,256] @ [256,256]  (fp16 MMA, half output)
    {
        dim3 grid(En / 128, (Mv + 127) / 128);
        gemm_f16v<<<grid, 256>>>(value, wt_s, b_v, vh_s, Mv, En, En);
    }
    // 2) combined offset+logit projection: [7200,256] @ [256,384]  (tf32, BM=64)
    {
        dim3 grid(384 / 128, (BQn + 63) / 64);
        gemm_tf32<<<grid, 256>>>(query, wc_s, bc_s, nullptr, olg_s, BQn, 384, En);
    }
    // 3) softmax + deformable bilinear sampling (half2 gathers, 128 thr/blk)
    msda_sample<<<BQn, 128>>>(olg_s, refpts, vh_s, mid_s);
    // 4) output projection + residual: [7200,256] @ [256,256] + query  (tf32, BM=64)
    {
        dim3 grid(En / 128, (BQn + 63) / 64);
        gemm_tf32<<<grid, 256>>>(mid_s, W_out, b_out, query, out, BQn, En, En);
    }
}

// round 14
// speedup vs baseline: 1.8868x; 1.0459x over previous
#include <cuda_runtime.h>
#include <cuda_fp16.h>
#include <cstdint>
#include <cstddef>

// Problem constants
#define Bn   8
#define Qn   900
#define En   256
#define NHn  8
#define HDn  32
#define NLn  4
#define NPn  4
#define Sn   19560
#define BQn  (Bn * Qn)          // 7200
#define Mv   (Bn * Sn)          // 156480

// Scratch (static device globals)
__device__ __half g_vh[(size_t)Bn * Sn * En];    // projected values [B,S,E] fp16
__device__ __half g_wt[(size_t)En * En];         // W_v^T   half [n][k]
__device__ __half g_wot[(size_t)En * En];        // W_out^T half [n][k]
__device__ __half g_wcq[(size_t)384 * En];       // [W_off | W_attn]^T half [n=384][k]
__device__ float g_bc[384];                      // b_off || b_attn
__device__ float g_offlg[(size_t)BQn * 384];     // [off(256) | logits(128)] per row
__device__ float g_mid[(size_t)BQn * En];

// ---------------------------------------------------------------------------
// Fused prologue: transpose+fp16-convert all weight matrices into K-major
// [n][k] layout, plus bias concat. One launch, 225 blocks of 32x8.
//   blocks   0- 63 : W_v   (256x256) -> g_wt
//   blocks  64-127 : W_out (256x256) -> g_wot
//   blocks 128-191 : W_off (256x256) -> g_wcq rows 0..255
//   blocks 192-223 : W_attn(256x128) -> g_wcq rows 256..383
//   block  224     : bias concat
// ---------------------------------------------------------------------------
__global__ void prep_weights(const float* __restrict__ W_v, const float* __restrict__ W_out,
                             const float* __restrict__ W_off, const float* __restrict__ b_off,
                             const float* __restrict__ W_attn, const float* __restrict__ b_attn,
                             __half* __restrict__ Wvt, __half* __restrict__ Wot,
                             __half* __restrict__ Wcq, float* __restrict__ bc)
{
    const int blk = blockIdx.x;
    const int tx = threadIdx.x, ty = threadIdx.y;   // 32 x 8

    if (blk == 224) {
        for (int i = ty * 32 + tx; i < 384; i += 256)
            bc[i] = (i < 256) ? b_off[i] : b_attn[i - 256];
        return;
    }

    __shared__ float tile[32][33];
    const float* src;
    __half* dst;
    int bx, by, srcN;
    if (blk < 64)       { src = W_v;    dst = Wvt;                 int u = blk;       bx = (u & 7) * 32; by = (u >> 3) * 32; srcN = 256; }
    else if (blk < 128) { src = W_out;  dst = Wot;                 int u = blk - 64;  bx = (u & 7) * 32; by = (u >> 3) * 32; srcN = 256; }
    else if (blk < 192) { src = W_off;  dst = Wcq;                 int u = blk - 128; bx = (u & 7) * 32; by = (u >> 3) * 32; srcN = 256; }
    else                { src = W_attn; dst = Wcq + (size_t)256 * 256; int u = blk - 192; bx = (u & 3) * 32; by = (u >> 2) * 32; srcN = 128; }

#pragma unroll
    for (int i = 0; i < 32; i += 8)
        tile[ty + i][tx] = src[(size_t)(by + ty + i) * srcN + bx + tx];
    __syncthreads();
#pragma unroll
    for (int i = 0; i < 32; i += 8)
        dst[(size_t)(bx + ty + i) * 256 + by + tx] = __float2half_rn(tile[tx][ty + i]);
}

// ---------------------------------------------------------------------------
// fp16 mma.sync helper
// ---------------------------------------------------------------------------
__device__ __forceinline__ void mma_f16(float* c, const uint32_t* a, const uint32_t* b) {
    asm volatile(
        "mma.sync.aligned.m16n8k16.row.col.f32.f16.f16.f32 "
        "{%0,%1,%2,%3}, {%4,%5,%6,%7}, {%8,%9}, {%0,%1,%2,%3};"
        : "+f"(c[0]), "+f"(c[1]), "+f"(c[2]), "+f"(c[3])
        : "r"(a[0]), "r"(a[1]), "r"(a[2]), "r"(a[3]), "r"(b[0]), "r"(b[1]));
}

// ---------------------------------------------------------------------------
// Value projection fp16 GEMM — round-8 proven. C_half = A_f32 @ Wt^T + bias.
// CTA 128x128, 8 warps 2x4.
// ---------------------------------------------------------------------------
__global__ __launch_bounds__(256, 2)
void gemm_f16v(const float* __restrict__ A, const __half* __restrict__ Wt,
               const float* __restrict__ bias, __half* __restrict__ C,
               int M, int N, int K)
{
    __shared__ __half As[128][40];
    __shared__ __half Bsn[128][40];

    const int tid  = threadIdx.x;
    const int lane = tid & 31;
    const int wid  = tid >> 5;
    const int wm   = wid >> 2;
    const int wn   = wid & 3;
    const int g    = lane >> 2;
    const int tg   = lane & 3;
    const int m0   = blockIdx.y * 128;
    const int n0   = blockIdx.x * 128;

    float c[4][4][4];
#pragma unroll
    for (int i = 0; i < 4; i++)
#pragma unroll
        for (int j = 0; j < 4; j++)
#pragma unroll
            for (int r = 0; r < 4; r++) c[i][j][r] = 0.0f;

    const int a_kq = tid & 7;
    const int a_m  = tid >> 3;
    const int b_nr = tid >> 2;
    const int b_q  = tid & 3;

    for (int k0 = 0; k0 < K; k0 += 32) {
#pragma unroll
        for (int i = 0; i < 4; i++) {
            int m = a_m + 32 * i;
            float4 v = make_float4(0.f, 0.f, 0.f, 0.f);
            if (m0 + m < M) v = *(const float4*)(A + (size_t)(m0 + m) * K + k0 + a_kq * 4);
            __half2 h01 = __floats2half2_rn(v.x, v.y);
            __half2 h23 = __floats2half2_rn(v.z, v.w);
            uint2 pk;
            pk.x = *(uint32_t*)&h01;
            pk.y = *(uint32_t*)&h23;
            *(uint2*)&As[m][a_kq * 4] = pk;
        }
#pragma unroll
        for (int i = 0; i < 2; i++) {
            int n = b_nr + 64 * i;
            uint4 v = *(const uint4*)(Wt + (size_t)(n0 + n) * K + k0 + b_q * 8);
            *(uint4*)&Bsn[n][b_q * 8] = v;
        }
        __syncthreads();

#pragma unroll
        for (int kk = 0; kk < 2; kk++) {
            uint32_t a[4][4], b[4][2];
#pragma unroll
            for (int mf = 0; mf < 4; mf++) {
                int m = wm * 64 + mf * 16 + g;
                a[mf][0] = *(const uint32_t*)&As[m][kk * 16 + 2 * tg];
                a[mf][1] = *(const uint32_t*)&As[m + 8][kk * 16 + 2 * tg];
                a[mf][2] = *(const uint32_t*)&As[m][kk * 16 + 2 * tg + 8];
                a[mf][3] = *(const uint32_t*)&As[m + 8][kk * 16 + 2 * tg + 8];
            }
#pragma unroll
            for (int nf = 0; nf < 4; nf++) {
                int n = wn * 32 + nf * 8 + g;
                b[nf][0] = *(const uint32_t*)&Bsn[n][kk * 16 + 2 * tg];
                b[nf][1] = *(const uint32_t*)&Bsn[n][kk * 16 + 2 * tg + 8];
            }
#pragma unroll
            for (int mf = 0; mf < 4; mf++)
#pragma unroll
                for (int nf = 0; nf < 4; nf++)
                    mma_f16(c[mf][nf], a[mf], b[nf]);
        }
        __syncthreads();
    }

#pragma unroll
    for (int mf = 0; mf < 4; mf++) {
        const int r0 = m0 + wm * 64 + mf * 16 + g;
        const int r1 = r0 + 8;
#pragma unroll
        for (int nf = 0; nf < 4; nf++) {
            const int cb = n0 + wn * 32 + nf * 8 + 2 * tg;
            const float bx = bias[cb], by = bias[cb + 1];
            if (r0 < M) {
                __half2 o = __floats2half2_rn(c[mf][nf][0] + bx, c[mf][nf][1] + by);
                *(__half2*)(C + (size_t)r0 * N + cb) = o;
            }
            if (r1 < M) {
                __half2 o = __floats2half2_rn(c[mf][nf][2] + bx, c[mf][nf][3] + by);
                *(__half2*)(C + (size_t)r1 * N + cb) = o;
            }
        }
    }
}

// ---------------------------------------------------------------------------
// fp16 GEMM for the query-path projections (fp32 in/out).
// C_f32[M,N] = A_f32[M,K] @ Bt_h^T + bias (+resid).  Bt is half [n][k].
// BM=64, BN=128, K-chunk 32; 8 warps 2x4, warp tile 32x32.
// Fragment layout identical to gemm_f16v; epilogue from proven BM64 kernel.
// ---------------------------------------------------------------------------
__global__ __launch_bounds__(256, 4)
void gemm_f16q(const float* __restrict__ A, const __half* __restrict__ Bt,
               const float* __restrict__ bias, const float* __restrict__ resid,
               float* __restrict__ C, int M, int N, int K)
{
    __shared__ __half As[64][40];
    __shared__ __half Bsn[128][40];

    const int tid  = threadIdx.x;
    const int lane = tid & 31;
    const int wid  = tid >> 5;
    const int wm   = wid >> 2;          // 0..1
    const int wn   = wid & 3;           // 0..3
    const int g    = lane >> 2;
    const int tg   = lane & 3;
    const int m0   = blockIdx.y * 64;
    const int n0   = blockIdx.x * 128;

    float c[2][4][4];
#pragma unroll
    for (int i = 0; i < 2; i++)
#pragma unroll
        for (int j = 0; j < 4; j++)
#pragma unroll
            for (int r = 0; r < 4; r++) c[i][j][r] = 0.0f;

    const int a_kq = tid & 7;           // float4 col in K-chunk
    const int a_m  = tid >> 3;          // 0..31
    const int b_nr = tid >> 2;          // 0..63
    const int b_q  = tid & 3;           // uint4 index in 32-k row

    for (int k0 = 0; k0 < K; k0 += 32) {
        // A tile 64x32 fp32 -> half
#pragma unroll
        for (int i = 0; i < 2; i++) {
            int m = a_m + 32 * i;
            float4 v = make_float4(0.f, 0.f, 0.f, 0.f);
            if (m0 + m < M) v = *(const float4*)(A + (size_t)(m0 + m) * K + k0 + a_kq * 4);
            __half2 h01 = __floats2half2_rn(v.x, v.y);
            __half2 h23 = __floats2half2_rn(v.z, v.w);
            uint2 pk;
            pk.x = *(uint32_t*)&h01;
            pk.y = *(uint32_t*)&h23;
            *(uint2*)&As[m][a_kq * 4] = pk;
        }
        // B tile 128x32: direct copy from half [n][k]
#pragma unroll
        for (int i = 0; i < 2; i++) {
            int n = b_nr + 64 * i;
            uint4 v = *(const uint4*)(Bt + (size_t)(n0 + n) * K + k0 + b_q * 8);
            *(uint4*)&Bsn[n][b_q * 8] = v;
        }
        __syncthreads();

#pragma unroll
        for (int kk = 0; kk < 2; kk++) {
            uint32_t a[2][4], b[4][2];
#pragma unroll
            for (int mf = 0; mf < 2; mf++) {
                int m = wm * 32 + mf * 16 + g;
                a[mf][0] = *(const uint32_t*)&As[m][kk * 16 + 2 * tg];
                a[mf][1] = *(const uint32_t*)&As[m + 8][kk * 16 + 2 * tg];
                a[mf][2] = *(const uint32_t*)&As[m][kk * 16 + 2 * tg + 8];
                a[mf][3] = *(const uint32_t*)&As[m + 8][kk * 16 + 2 * tg + 8];
            }
#pragma unroll
            for (int nf = 0; nf < 4; nf++) {
                int n = wn * 32 + nf * 8 + g;
                b[nf][0] = *(const uint32_t*)&Bsn[n][kk * 16 + 2 * tg];
                b[nf][1] = *(const uint32_t*)&Bsn[n][kk * 16 + 2 * tg + 8];
            }
#pragma unroll
            for (int mf = 0; mf < 2; mf++)
#pragma unroll
                for (int nf = 0; nf < 4; nf++)
                    mma_f16(c[mf][nf], a[mf], b[nf]);
        }
        __syncthreads();
    }

#pragma unroll
    for (int mf = 0; mf < 2; mf++) {
        const int r0 = m0 + wm * 32 + mf * 16 + g;
        const int r1 = r0 + 8;
#pragma unroll
        for (int nf = 0; nf < 4; nf++) {
            const int cb = n0 + wn * 32 + nf * 8 + 2 * tg;
            const float bx = bias[cb], by = bias[cb + 1];
            if (r0 < M) {
                float2 o = make_float2(c[mf][nf][0] + bx, c[mf][nf][1] + by);
                if (resid) {
                    const float2 rr = *(const float2*)(resid + (size_t)r0 * N + cb);
                    o.x += rr.x; o.y += rr.y;
                }
                *(float2*)(C + (size_t)r0 * N + cb) = o;
            }
            if (r1 < M) {
                float2 o = make_float2(c[mf][nf][2] + bx, c[mf][nf][3] + by);
                if (resid) {
                    const float2 rr = *(const float2*)(resid + (size_t)r1 * N + cb);
                    o.x += rr.x; o.y += rr.y;
                }
                *(float2*)(C + (size_t)r1 * N + cb) = o;
            }
        }
    }
}

// ---------------------------------------------------------------------------
// Fused softmax + deformable sampling — round-13 proven (half2 gathers).
// ---------------------------------------------------------------------------
__global__ __launch_bounds__(128, 12)
void msda_sample(const float* __restrict__ offlg, const float* __restrict__ ref,
                 const __half* __restrict__ v, float* __restrict__ mid)
{
    const int lvlH[NLn]     = {92, 46, 23, 12};
    const int lvlW[NLn]     = {160, 80, 40, 20};
    const int lvlStart[NLn] = {0, 14720, 18400, 19320};

    const int row = blockIdx.x;
    const int b   = row / Qn;
    const int t   = threadIdx.x;   // 0..127

    __shared__ float s_loc[256];
    __shared__ float s_lg[128];
    __shared__ int4   s_idx[128];
    __shared__ float4 s_wgt[128];

    const float* __restrict__ rowp = offlg + (size_t)row * 384;

#pragma unroll
    for (int i = 0; i < 2; i++) {
        const int idx = t + i * 128;
        const int c = idx & 1;
        const int l = (idx >> 3) & 3;
        const float dim = (c == 0) ? (float)lvlW[l] : (float)lvlH[l];
        const float r = ref[((size_t)row * NLn + l) * 2 + c];
        s_loc[idx] = r * dim - 0.5f + rowp[idx];
    }
    s_lg[t] = rowp[256 + t];
    __syncthreads();

    {
        const int h = t >> 4;
        float m = -1e30f;
#pragma unroll
        for (int i = 0; i < 16; i++) m = fmaxf(m, s_lg[h * 16 + i]);
        float sum = 0.0f;
#pragma unroll
        for (int i = 0; i < 16; i++) sum += __expf(s_lg[h * 16 + i] - m);
        const float w = __expf(s_lg[t] - m) / sum;

        const int l = (t >> 2) & 3;
        const int Hl = lvlH[l], Wl = lvlW[l], base = lvlStart[l];
        const float x = s_loc[t * 2 + 0];
        const float y = s_loc[t * 2 + 1];
        const float xf = floorf(x), yf = floorf(y);
        const float wx = x - xf, wy = y - yf;
        const int x0 = (int)xf, y0 = (int)yf, x1 = x0 + 1, y1 = y0 + 1;

        const bool vx0 = (x0 >= 0) & (x0 < Wl), vx1 = (x1 >= 0) & (x1 < Wl);
        const bool vy0 = (y0 >= 0) & (y0 < Hl), vy1 = (y1 >= 0) & (y1 < Hl);
        const int xc0 = min(max(x0, 0), Wl - 1), xc1 = min(max(x1, 0), Wl - 1);
        const int yc0 = min(max(y0, 0), Hl - 1), yc1 = min(max(y1, 0), Hl - 1);

        int4 id;
        id.x = base + yc0 * Wl + xc0;
        id.y = base + yc0 * Wl + xc1;
        id.z = base + yc1 * Wl + xc0;
        id.w = base + yc1 * Wl + xc1;
        s_idx[t] = id;
        float4 ww;
        ww.x = (vy0 & vx0) ? w * (1.f - wy) * (1.f - wx) : 0.f;
        ww.y = (vy0 & vx1) ? w * (1.f - wy) * wx : 0.f;
        ww.z = (vy1 & vx0) ? w * wy * (1.f - wx) : 0.f;
        ww.w = (vy1 & vx1) ? w * wy * wx : 0.f;
        s_wgt[t] = ww;
    }
    __syncthreads();

    const int h  = t >> 4;
    const int dp = t & 15;
    const __half* __restrict__ vb = v + (size_t)b * Sn * En + h * HDn + dp * 2;

    float accx = 0.0f, accy = 0.0f;
#pragma unroll
    for (int s = 0; s < 16; s++) {
        const int si = h * 16 + s;
        const int4   id = s_idx[si];
        const float4 ww = s_wgt[si];
        float2 f0 = __half22float2(*(const __half2*)(vb + (size_t)id.x * En));
        float2 f1 = __half22float2(*(const __half2*)(vb + (size_t)id.y * En));
        float2 f2 = __half22float2(*(const __half2*)(vb + (size_t)id.z * En));
        float2 f3 = __half22float2(*(const __half2*)(vb + (size_t)id.w * En));
        accx += ww.x * f0.x + ww.y * f1.x + ww.z * f2.x + ww.w * f3.x;
        accy += ww.x * f0.y + ww.y * f1.y + ww.z * f2.y + ww.w * f3.y;
    }

    *(float2*)(mid + (size_t)row * En + h * HDn + dp * 2) = make_float2(accx, accy);
}

// ---------------------------------------------------------------------------
extern "C" void kernel_launch(void* const* d_in, const int* in_sizes, int n_in,
                              void* d_out, int out_size)
{
    const float* query  = (const float*)d_in[0];
    const float* value  = (const float*)d_in[1];
    const float* refpts = (const float*)d_in[2];
    const float* W_off  = (const float*)d_in[4];
    const float* b_off  = (const float*)d_in[5];
    const float* W_attn = (const float*)d_in[6];
    const float* b_attn = (const float*)d_in[7];
    const float* W_v    = (const float*)d_in[8];
    const float* b_v    = (const float*)d_in[9];
    const float* W_out  = (const float*)d_in[10];
    const float* b_out  = (const float*)d_in[11];
    float* out = (float*)d_out;

    void *pvh, *pwt, *pwot, *pwcq, *pbc, *polg, *pmid;
    cudaGetSymbolAddress(&pvh, g_vh);
    cudaGetSymbolAddress(&pwt, g_wt);
    cudaGetSymbolAddress(&pwot, g_wot);
    cudaGetSymbolAddress(&pwcq, g_wcq);
    cudaGetSymbolAddress(&pbc, g_bc);
    cudaGetSymbolAddress(&polg, g_offlg);
    cudaGetSymbolAddress(&pmid, g_mid);
    __half* vh_s  = (__half*)pvh;
    __half* wt_s  = (__half*)pwt;
    __half* wot_s = (__half*)pwot;
    __half* wcq_s = (__half*)pwcq;
    float* bc_s   = (float*)pbc;
    float* olg_s  = (float*)polg;
    float* mid_s  = (float*)pmid;

    // 0) fused weight prep (transpose + fp16 convert + bias concat)
    prep_weights<<<225, dim3(32, 8)>>>(W_v, W_out, W_off, b_off, W_attn, b_attn,
                                       wt_s, wot_s, wcq_s, bc_s);

    // 1) value projection: [156480,256] @ [256,256]  (fp16 MMA, half output)
    {
        dim3 grid(En / 128, (Mv + 127) / 128);
        gemm_f16v<<<grid, 256>>>(value, wt_s, b_v, vh_s, Mv, En, En);
    }
    // 2) combined offset+logit projection: [7200,256] @ [256,384]  (fp16, BM=64)
    {
        dim3 grid(384 / 128, (BQn + 63) / 64);
        gemm_f16q<<<grid, 256>>>(query, wcq_s, bc_s, nullptr, olg_s, BQn, 384, En);
    }
    // 3) softmax + deformable bilinear sampling (half2 gathers)
    msda_sample<<<BQn, 128>>>(olg_s, refpts, vh_s, mid_s);
    // 4) output projection + residual: [7200,256] @ [256,256] + query  (fp16, BM=64)
    {
        dim3 grid(En / 128, (BQn + 63) / 64);
        gemm_f16q<<<grid, 256>>>(mid_s, wot_s, b_out, query, out, BQn, En, En);
    }
}

// round 15
// speedup vs baseline: 2.1265x; 1.1270x over previous
#include <cuda_runtime.h>
#include <cuda_fp16.h>
#include <cstdint>
#include <cstddef>

// Problem constants
#define Bn   8
#define Qn   900
#define En   256
#define NHn  8
#define HDn  32
#define NLn  4
#define NPn  4
#define Sn   19560
#define BQn  (Bn * Qn)          // 7200
#define Mv   (Bn * Sn)          // 156480

// Scratch (static device globals)
__device__ __half g_vh[(size_t)Bn * Sn * En];    // projected values [B,S,E] fp16
__device__ __half g_wt[(size_t)En * En];         // W_v^T   half [n][k]
__device__ __half g_wot[(size_t)En * En];        // W_out^T half [n][k]
__device__ __half g_wcq[(size_t)384 * En];       // [W_off | W_attn]^T half [n=384][k]
__device__ float g_bc[384];                      // b_off || b_attn
__device__ float g_offlg[(size_t)BQn * 384];     // [off(256) | logits(128)] per row
__device__ float g_mid[(size_t)BQn * En];

// ---------------------------------------------------------------------------
// cp.async helpers
// ---------------------------------------------------------------------------
__device__ __forceinline__ void cp_async16(void* smem_dst, const void* gsrc, int src_bytes) {
    uint32_t d = (uint32_t)__cvta_generic_to_shared(smem_dst);
    asm volatile("cp.async.cg.shared.global [%0], [%1], 16, %2;"
                 :: "r"(d), "l"(gsrc), "r"(src_bytes) : "memory");
}
#define CP_ASYNC_COMMIT() asm volatile("cp.async.commit_group;" ::: "memory")
#define CP_ASYNC_WAIT1()  asm volatile("cp.async.wait_group 1;" ::: "memory")
#define CP_ASYNC_WAIT0()  asm volatile("cp.async.wait_group 0;" ::: "memory")

// ---------------------------------------------------------------------------
// Fused prologue: transpose+fp16-convert weights + bias concat (proven).
// ---------------------------------------------------------------------------
__global__ void prep_weights(const float* __restrict__ W_v, const float* __restrict__ W_out,
                             const float* __restrict__ W_off, const float* __restrict__ b_off,
                             const float* __restrict__ W_attn, const float* __restrict__ b_attn,
                             __half* __restrict__ Wvt, __half* __restrict__ Wot,
                             __half* __restrict__ Wcq, float* __restrict__ bc)
{
    const int blk = blockIdx.x;
    const int tx = threadIdx.x, ty = threadIdx.y;   // 32 x 8

    if (blk == 224) {
        for (int i = ty * 32 + tx; i < 384; i += 256)
            bc[i] = (i < 256) ? b_off[i] : b_attn[i - 256];
        return;
    }

    __shared__ float tile[32][33];
    const float* src;
    __half* dst;
    int bx, by, srcN;
    if (blk < 64)       { src = W_v;    dst = Wvt;                 int u = blk;       bx = (u & 7) * 32; by = (u >> 3) * 32; srcN = 256; }
    else if (blk < 128) { src = W_out;  dst = Wot;                 int u = blk - 64;  bx = (u & 7) * 32; by = (u >> 3) * 32; srcN = 256; }
    else if (blk < 192) { src = W_off;  dst = Wcq;                 int u = blk - 128; bx = (u & 7) * 32; by = (u >> 3) * 32; srcN = 256; }
    else                { src = W_attn; dst = Wcq + (size_t)256 * 256; int u = blk - 192; bx = (u & 3) * 32; by = (u >> 2) * 32; srcN = 128; }

#pragma unroll
    for (int i = 0; i < 32; i += 8)
        tile[ty + i][tx] = src[(size_t)(by + ty + i) * srcN + bx + tx];
    __syncthreads();
#pragma unroll
    for (int i = 0; i < 32; i += 8)
        dst[(size_t)(bx + ty + i) * 256 + by + tx] = __float2half_rn(tile[tx][ty + i]);
}

// ---------------------------------------------------------------------------
// fp16 mma.sync helper
// ---------------------------------------------------------------------------
__device__ __forceinline__ void mma_f16(float* c, const uint32_t* a, const uint32_t* b) {
    asm volatile(
        "mma.sync.aligned.m16n8k16.row.col.f32.f16.f16.f32 "
        "{%0,%1,%2,%3}, {%4,%5,%6,%7}, {%8,%9}, {%0,%1,%2,%3};"
        : "+f"(c[0]), "+f"(c[1]), "+f"(c[2]), "+f"(c[3])
        : "r"(a[0]), "r"(a[1]), "r"(a[2]), "r"(a[3]), "r"(b[0]), "r"(b[1]));
}

// ---------------------------------------------------------------------------
// Value projection fp16 GEMM, cp.async double-buffered.
// A staged fp32 (rows padded to 40 floats -> conflict-free LDS.64 frag reads,
// cvt to half at fragment time). B staged half (rows padded to 56 halves =
// 112 B, 16B-aligned cp.async, conflict-free LDS.32 frag reads).
// CTA 128x128, 8 warps 2x4. Numerics identical to single-buffered version.
// ---------------------------------------------------------------------------
__global__ __launch_bounds__(256, 2)
void gemm_f16v(const float* __restrict__ A, const __half* __restrict__ Wt,
               const float* __restrict__ bias, __half* __restrict__ C,
               int M, int N, int K)
{
    __shared__ float  As[2][128][40];   // fp32 A stage
    __shared__ __half Bsn[2][128][56];  // half B stage [n][k]

    const int tid  = threadIdx.x;
    const int lane = tid & 31;
    const int wid  = tid >> 5;
    const int wm   = wid >> 2;
    const int wn   = wid & 3;
    const int g    = lane >> 2;
    const int tg   = lane & 3;
    const int m0   = blockIdx.y * 128;
    const int n0   = blockIdx.x * 128;

    float c[4][4][4];
#pragma unroll
    for (int i = 0; i < 4; i++)
#pragma unroll
        for (int j = 0; j < 4; j++)
#pragma unroll
            for (int r = 0; r < 4; r++) c[i][j][r] = 0.0f;

    const int a_kq = tid & 7;           // float4 col within K-chunk
    const int a_m  = tid >> 3;          // 0..31
    const int b_nr = tid >> 2;          // 0..63
    const int b_q  = tid & 3;           // 8-half block in 32-k row

    const int NC = K / 32;

    auto load_chunk = [&](int k0, int buf) {
#pragma unroll
        for (int i = 0; i < 4; i++) {
            int m = a_m + 32 * i;
            int gm = m0 + m;
            int ok = (gm < M) ? 16 : 0;
            int gmc = (gm < M) ? gm : 0;
            cp_async16(&As[buf][m][a_kq * 4], A + (size_t)gmc * K + k0 + a_kq * 4, ok);
        }
#pragma unroll
        for (int i = 0; i < 2; i++) {
            int n = b_nr + 64 * i;
            cp_async16(&Bsn[buf][n][b_q * 8], Wt + (size_t)(n0 + n) * K + k0 + b_q * 8, 16);
        }
        CP_ASYNC_COMMIT();
    };

    load_chunk(0, 0);

    for (int cidx = 0; cidx < NC; cidx++) {
        const int buf = cidx & 1;
        if (cidx + 1 < NC) {
            load_chunk((cidx + 1) * 32, (cidx + 1) & 1);
            CP_ASYNC_WAIT1();
        } else {
            CP_ASYNC_WAIT0();
        }
        __syncthreads();

#pragma unroll
        for (int kk = 0; kk < 2; kk++) {
            uint32_t a[4][4], b[4][2];
#pragma unroll
            for (int mf = 0; mf < 4; mf++) {
                int m = wm * 64 + mf * 16 + g;
                float2 f0 = *(const float2*)&As[buf][m][kk * 16 + 2 * tg];
                float2 f1 = *(const float2*)&As[buf][m + 8][kk * 16 + 2 * tg];
                float2 f2 = *(const float2*)&As[buf][m][kk * 16 + 2 * tg + 8];
                float2 f3 = *(const float2*)&As[buf][m + 8][kk * 16 + 2 * tg + 8];
                __half2 h0 = __floats2half2_rn(f0.x, f0.y);
                __half2 h1 = __floats2half2_rn(f1.x, f1.y);
                __half2 h2 = __floats2half2_rn(f2.x, f2.y);
                __half2 h3 = __floats2half2_rn(f3.x, f3.y);
                a[mf][0] = *(uint32_t*)&h0;
                a[mf][1] = *(uint32_t*)&h1;
                a[mf][2] = *(uint32_t*)&h2;
                a[mf][3] = *(uint32_t*)&h3;
            }
#pragma unroll
            for (int nf = 0; nf < 4; nf++) {
                int n = wn * 32 + nf * 8 + g;
                b[nf][0] = *(const uint32_t*)&Bsn[buf][n][kk * 16 + 2 * tg];
                b[nf][1] = *(const uint32_t*)&Bsn[buf][n][kk * 16 + 2 * tg + 8];
            }
#pragma unroll
            for (int mf = 0; mf < 4; mf++)
#pragma unroll
                for (int nf = 0; nf < 4; nf++)
                    mma_f16(c[mf][nf], a[mf], b[nf]);
        }
        __syncthreads();
    }

#pragma unroll
    for (int mf = 0; mf < 4; mf++) {
        const int r0 = m0 + wm * 64 + mf * 16 + g;
        const int r1 = r0 + 8;
#pragma unroll
        for (int nf = 0; nf < 4; nf++) {
            const int cb = n0 + wn * 32 + nf * 8 + 2 * tg;
            const float bx = bias[cb], by = bias[cb + 1];
            if (r0 < M) {
                __half2 o = __floats2half2_rn(c[mf][nf][0] + bx, c[mf][nf][1] + by);
                *(__half2*)(C + (size_t)r0 * N + cb) = o;
            }
            if (r1 < M) {
                __half2 o = __floats2half2_rn(c[mf][nf][2] + bx, c[mf][nf][3] + by);
                *(__half2*)(C + (size_t)r1 * N + cb) = o;
            }
        }
    }
}

// ---------------------------------------------------------------------------
// fp16 GEMM for the query-path projections — round-14 proven. Unchanged.
// ---------------------------------------------------------------------------
__global__ __launch_bounds__(256, 4)
void gemm_f16q(const float* __restrict__ A, const __half* __restrict__ Bt,
               const float* __restrict__ bias, const float* __restrict__ resid,
               float* __restrict__ C, int M, int N, int K)
{
    __shared__ __half As[64][40];
    __shared__ __half Bsn[128][40];

    const int tid  = threadIdx.x;
    const int lane = tid & 31;
    const int wid  = tid >> 5;
    const int wm   = wid >> 2;
    const int wn   = wid & 3;
    const int g    = lane >> 2;
    const int tg   = lane & 3;
    const int m0   = blockIdx.y * 64;
    const int n0   = blockIdx.x * 128;

    float c[2][4][4];
#pragma unroll
    for (int i = 0; i < 2; i++)
#pragma unroll
        for (int j = 0; j < 4; j++)
#pragma unroll
            for (int r = 0; r < 4; r++) c[i][j][r] = 0.0f;

    const int a_kq = tid & 7;
    const int a_m  = tid >> 3;
    const int b_nr = tid >> 2;
    const int b_q  = tid & 3;

    for (int k0 = 0; k0 < K; k0 += 32) {
#pragma unroll
        for (int i = 0; i < 2; i++) {
            int m = a_m + 32 * i;
            float4 v = make_float4(0.f, 0.f, 0.f, 0.f);
            if (m0 + m < M) v = *(const float4*)(A + (size_t)(m0 + m) * K + k0 + a_kq * 4);
            __half2 h01 = __floats2half2_rn(v.x, v.y);
            __half2 h23 = __floats2half2_rn(v.z, v.w);
            uint2 pk;
            pk.x = *(uint32_t*)&h01;
            pk.y = *(uint32_t*)&h23;
            *(uint2*)&As[m][a_kq * 4] = pk;
        }
#pragma unroll
        for (int i = 0; i < 2; i++) {
            int n = b_nr + 64 * i;
            uint4 v = *(const uint4*)(Bt + (size_t)(n0 + n) * K + k0 + b_q * 8);
            *(uint4*)&Bsn[n][b_q * 8] = v;
        }
        __syncthreads();

#pragma unroll
        for (int kk = 0; kk < 2; kk++) {
            uint32_t a[2][4], b[4][2];
#pragma unroll
            for (int mf = 0; mf < 2; mf++) {
                int m = wm * 32 + mf * 16 + g;
                a[mf][0] = *(const uint32_t*)&As[m][kk * 16 + 2 * tg];
                a[mf][1] = *(const uint32_t*)&As[m + 8][kk * 16 + 2 * tg];
                a[mf][2] = *(const uint32_t*)&As[m][kk * 16 + 2 * tg + 8];
                a[mf][3] = *(const uint32_t*)&As[m + 8][kk * 16 + 2 * tg + 8];
            }
#pragma unroll
            for (int nf = 0; nf < 4; nf++) {
                int n = wn * 32 + nf * 8 + g;
                b[nf][0] = *(const uint32_t*)&Bsn[n][kk * 16 + 2 * tg];
                b[nf][1] = *(const uint32_t*)&Bsn[n][kk * 16 + 2 * tg + 8];
            }
#pragma unroll
            for (int mf = 0; mf < 2; mf++)
#pragma unroll
                for (int nf = 0; nf < 4; nf++)
                    mma_f16(c[mf][nf], a[mf], b[nf]);
        }
        __syncthreads();
    }

#pragma unroll
    for (int mf = 0; mf < 2; mf++) {
        const int r0 = m0 + wm * 32 + mf * 16 + g;
        const int r1 = r0 + 8;
#pragma unroll
        for (int nf = 0; nf < 4; nf++) {
            const int cb = n0 + wn * 32 + nf * 8 + 2 * tg;
            const float bx = bias[cb], by = bias[cb + 1];
            if (r0 < M) {
                float2 o = make_float2(c[mf][nf][0] + bx, c[mf][nf][1] + by);
                if (resid) {
                    const float2 rr = *(const float2*)(resid + (size_t)r0 * N + cb);
                    o.x += rr.x; o.y += rr.y;
                }
                *(float2*)(C + (size_t)r0 * N + cb) = o;
            }
            if (r1 < M) {
                float2 o = make_float2(c[mf][nf][2] + bx, c[mf][nf][3] + by);
                if (resid) {
                    const float2 rr = *(const float2*)(resid + (size_t)r1 * N + cb);
                    o.x += rr.x; o.y += rr.y;
                }
                *(float2*)(C + (size_t)r1 * N + cb) = o;
            }
        }
    }
}

// ---------------------------------------------------------------------------
// Fused softmax + deformable sampling — round-13 proven (half2 gathers).
// ---------------------------------------------------------------------------
__global__ __launch_bounds__(128, 12)
void msda_sample(const float* __restrict__ offlg, const float* __restrict__ ref,
                 const __half* __restrict__ v, float* __restrict__ mid)
{
    const int lvlH[NLn]     = {92, 46, 23, 12};
    const int lvlW[NLn]     = {160, 80, 40, 20};
    const int lvlStart[NLn] = {0, 14720, 18400, 19320};

    const int row = blockIdx.x;
    const int b   = row / Qn;
    const int t   = threadIdx.x;   // 0..127

    __shared__ float s_loc[256];
    __shared__ float s_lg[128];
    __shared__ int4   s_idx[128];
    __shared__ float4 s_wgt[128];

    const float* __restrict__ rowp = offlg + (size_t)row * 384;

#pragma unroll
    for (int i = 0; i < 2; i++) {
        const int idx = t + i * 128;
        const int c = idx & 1;
        const int l = (idx >> 3) & 3;
        const float dim = (c == 0) ? (float)lvlW[l] : (float)lvlH[l];
        const float r = ref[((size_t)row * NLn + l) * 2 + c];
        s_loc[idx] = r * dim - 0.5f + rowp[idx];
    }
    s_lg[t] = rowp[256 + t];
    __syncthreads();

    {
        const int h = t >> 4;
        float m = -1e30f;
#pragma unroll
        for (int i = 0; i < 16; i++) m = fmaxf(m, s_lg[h * 16 + i]);
        float sum = 0.0f;
#pragma unroll
        for (int i = 0; i < 16; i++) sum += __expf(s_lg[h * 16 + i] - m);
        const float w = __expf(s_lg[t] - m) / sum;

        const int l = (t >> 2) & 3;
        const int Hl = lvlH[l], Wl = lvlW[l], base = lvlStart[l];
        const float x = s_loc[t * 2 + 0];
        const float y = s_loc[t * 2 + 1];
        const float xf = floorf(x), yf = floorf(y);
        const float wx = x - xf, wy = y - yf;
        const int x0 = (int)xf, y0 = (int)yf, x1 = x0 + 1, y1 = y0 + 1;

        const bool vx0 = (x0 >= 0) & (x0 < Wl), vx1 = (x1 >= 0) & (x1 < Wl);
        const bool vy0 = (y0 >= 0) & (y0 < Hl), vy1 = (y1 >= 0) & (y1 < Hl);
        const int xc0 = min(max(x0, 0), Wl - 1), xc1 = min(max(x1, 0), Wl - 1);
        const int yc0 = min(max(y0, 0), Hl - 1), yc1 = min(max(y1, 0), Hl - 1);

        int4 id;
        id.x = base + yc0 * Wl + xc0;
        id.y = base + yc0 * Wl + xc1;
        id.z = base + yc1 * Wl + xc0;
        id.w = base + yc1 * Wl + xc1;
        s_idx[t] = id;
        float4 ww;
        ww.x = (vy0 & vx0) ? w * (1.f - wy) * (1.f - wx) : 0.f;
        ww.y = (vy0 & vx1) ? w * (1.f - wy) * wx : 0.f;
        ww.z = (vy1 & vx0) ? w * wy * (1.f - wx) : 0.f;
        ww.w = (vy1 & vx1) ? w * wy * wx : 0.f;
        s_wgt[t] = ww;
    }
    __syncthreads();

    const int h  = t >> 4;
    const int dp = t & 15;
    const __half* __restrict__ vb = v + (size_t)b * Sn * En + h * HDn + dp * 2;

    float accx = 0.0f, accy = 0.0f;
#pragma unroll
    for (int s = 0; s < 16; s++) {
        const int si = h * 16 + s;
        const int4   id = s_idx[si];
        const float4 ww = s_wgt[si];
        float2 f0 = __half22float2(*(const __half2*)(vb + (size_t)id.x * En));
        float2 f1 = __half22float2(*(const __half2*)(vb + (size_t)id.y * En));
        float2 f2 = __half22float2(*(const __half2*)(vb + (size_t)id.z * En));
        float2 f3 = __half22float2(*(const __half2*)(vb + (size_t)id.w * En));
        accx += ww.x * f0.x + ww.y * f1.x + ww.z * f2.x + ww.w * f3.x;
        accy += ww.x * f0.y + ww.y * f1.y + ww.z * f2.y + ww.w * f3.y;
    }

    *(float2*)(mid + (size_t)row * En + h * HDn + dp * 2) = make_float2(accx, accy);
}

// ---------------------------------------------------------------------------
extern "C" void kernel_launch(void* const* d_in, const int* in_sizes, int n_in,
                              void* d_out, int out_size)
{
    const float* query  = (const float*)d_in[0];
    const float* value  = (const float*)d_in[1];
    const float* refpts = (const float*)d_in[2];
    const float* W_off  = (const float*)d_in[4];
    const float* b_off  = (const float*)d_in[5];
    const float* W_attn = (const float*)d_in[6];
    const float* b_attn = (const float*)d_in[7];
    const float* W_v    = (const float*)d_in[8];
    const float* b_v    = (const float*)d_in[9];
    const float* W_out  = (const float*)d_in[10];
    const float* b_out  = (const float*)d_in[11];
    float* out = (float*)d_out;

    void *pvh, *pwt, *pwot, *pwcq, *pbc, *polg, *pmid;
    cudaGetSymbolAddress(&pvh, g_vh);
    cudaGetSymbolAddress(&pwt, g_wt);
    cudaGetSymbolAddress(&pwot, g_wot);
    cudaGetSymbolAddress(&pwcq, g_wcq);
    cudaGetSymbolAddress(&pbc, g_bc);
    cudaGetSymbolAddress(&polg, g_offlg);
    cudaGetSymbolAddress(&pmid, g_mid);
    __half* vh_s  = (__half*)pvh;
    __half* wt_s  = (__half*)pwt;
    __half* wot_s = (__half*)pwot;
    __half* wcq_s = (__half*)pwcq;
    float* bc_s   = (float*)pbc;
    float* olg_s  = (float*)polg;
    float* mid_s  = (float*)pmid;

    // 0) fused weight prep (transpose + fp16 convert + bias concat)
    prep_weights<<<225, dim3(32, 8)>>>(W_v, W_out, W_off, b_off, W_attn, b_attn,
                                       wt_s, wot_s, wcq_s, bc_s);

    // 1) value projection: [156480,256] @ [256,256]  (fp16 MMA, cp.async)
    {
        dim3 grid(En / 128, (Mv + 127) / 128);
        gemm_f16v<<<grid, 256>>>(value, wt_s, b_v, vh_s, Mv, En, En);
    }
    // 2) combined offset+logit projection: [7200,256] @ [256,384]  (fp16, BM=64)
    {
        dim3 grid(384 / 128, (BQn + 63) / 64);
        gemm_f16q<<<grid, 256>>>(query, wcq_s, bc_s, nullptr, olg_s, BQn, 384, En);
    }
    // 3) softmax + deformable bilinear sampling (half2 gathers)
    msda_sample<<<BQn, 128>>>(olg_s, refpts, vh_s, mid_s);
    // 4) output projection + residual: [7200,256] @ [256,256] + query  (fp16, BM=64)
    {
        dim3 grid(En / 128, (BQn + 63) / 64);
        gemm_f16q<<<grid, 256>>>(mid_s, wot_s, b_out, query, out, BQn, En, En);
    }
}

// round 16
// speedup vs baseline: 2.1722x; 1.0215x over previous
#include <cuda_runtime.h>
#include <cuda_fp16.h>
#include <cstdint>
#include <cstddef>

// Problem constants
#define Bn   8
#define Qn   900
#define En   256
#define NHn  8
#define HDn  32
#define NLn  4
#define NPn  4
#define Sn   19560
#define BQn  (Bn * Qn)          // 7200
#define Mv   (Bn * Sn)          // 156480

// Scratch (static device globals)
__device__ __half g_vh[(size_t)Bn * Sn * En];    // projected values [B,S,E] fp16
__device__ __half g_wt[(size_t)En * En];         // W_v^T   half [n][k]
__device__ __half g_wot[(size_t)En * En];        // W_out^T half [n][k]
__device__ __half g_wcq[(size_t)384 * En];       // [W_off | W_attn]^T half [n=384][k]
__device__ float g_bc[384];                      // b_off || b_attn
__device__ float g_offlg[(size_t)BQn * 384];     // [off(256) | logits(128)] per row
__device__ float g_mid[(size_t)BQn * En];

// ---------------------------------------------------------------------------
// cp.async helpers
// ---------------------------------------------------------------------------
__device__ __forceinline__ void cp_async16(void* smem_dst, const void* gsrc, int src_bytes) {
    uint32_t d = (uint32_t)__cvta_generic_to_shared(smem_dst);
    asm volatile("cp.async.cg.shared.global [%0], [%1], 16, %2;"
                 :: "r"(d), "l"(gsrc), "r"(src_bytes) : "memory");
}
#define CP_ASYNC_COMMIT() asm volatile("cp.async.commit_group;" ::: "memory")
#define CP_ASYNC_WAIT1()  asm volatile("cp.async.wait_group 1;" ::: "memory")
#define CP_ASYNC_WAIT0()  asm volatile("cp.async.wait_group 0;" ::: "memory")

// ---------------------------------------------------------------------------
// Fused prologue: transpose+fp16-convert weights + bias concat (proven).
// ---------------------------------------------------------------------------
__global__ void prep_weights(const float* __restrict__ W_v, const float* __restrict__ W_out,
                             const float* __restrict__ W_off, const float* __restrict__ b_off,
                             const float* __restrict__ W_attn, const float* __restrict__ b_attn,
                             __half* __restrict__ Wvt, __half* __restrict__ Wot,
                             __half* __restrict__ Wcq, float* __restrict__ bc)
{
    const int blk = blockIdx.x;
    const int tx = threadIdx.x, ty = threadIdx.y;   // 32 x 8

    if (blk == 224) {
        for (int i = ty * 32 + tx; i < 384; i += 256)
            bc[i] = (i < 256) ? b_off[i] : b_attn[i - 256];
        return;
    }

    __shared__ float tile[32][33];
    const float* src;
    __half* dst;
    int bx, by, srcN;
    if (blk < 64)       { src = W_v;    dst = Wvt;                 int u = blk;       bx = (u & 7) * 32; by = (u >> 3) * 32; srcN = 256; }
    else if (blk < 128) { src = W_out;  dst = Wot;                 int u = blk - 64;  bx = (u & 7) * 32; by = (u >> 3) * 32; srcN = 256; }
    else if (blk < 192) { src = W_off;  dst = Wcq;                 int u = blk - 128; bx = (u & 7) * 32; by = (u >> 3) * 32; srcN = 256; }
    else                { src = W_attn; dst = Wcq + (size_t)256 * 256; int u = blk - 192; bx = (u & 3) * 32; by = (u >> 2) * 32; srcN = 128; }

#pragma unroll
    for (int i = 0; i < 32; i += 8)
        tile[ty + i][tx] = src[(size_t)(by + ty + i) * srcN + bx + tx];
    __syncthreads();
#pragma unroll
    for (int i = 0; i < 32; i += 8)
        dst[(size_t)(bx + ty + i) * 256 + by + tx] = __float2half_rn(tile[tx][ty + i]);
}

// ---------------------------------------------------------------------------
// fp16 mma.sync helper
// ---------------------------------------------------------------------------
__device__ __forceinline__ void mma_f16(float* c, const uint32_t* a, const uint32_t* b) {
    asm volatile(
        "mma.sync.aligned.m16n8k16.row.col.f32.f16.f16.f32 "
        "{%0,%1,%2,%3}, {%4,%5,%6,%7}, {%8,%9}, {%0,%1,%2,%3};"
        : "+f"(c[0]), "+f"(c[1]), "+f"(c[2]), "+f"(c[3])
        : "r"(a[0]), "r"(a[1]), "r"(a[2]), "r"(a[3]), "r"(b[0]), "r"(b[1]));
}

// ---------------------------------------------------------------------------
// Value projection fp16 GEMM, cp.async double-buffered — round-15 proven.
// ---------------------------------------------------------------------------
__global__ __launch_bounds__(256, 2)
void gemm_f16v(const float* __restrict__ A, const __half* __restrict__ Wt,
               const float* __restrict__ bias, __half* __restrict__ C,
               int M, int N, int K)
{
    __shared__ float  As[2][128][40];   // fp32 A stage
    __shared__ __half Bsn[2][128][56];  // half B stage [n][k]

    const int tid  = threadIdx.x;
    const int lane = tid & 31;
    const int wid  = tid >> 5;
    const int wm   = wid >> 2;
    const int wn   = wid & 3;
    const int g    = lane >> 2;
    const int tg   = lane & 3;
    const int m0   = blockIdx.y * 128;
    const int n0   = blockIdx.x * 128;

    float c[4][4][4];
#pragma unroll
    for (int i = 0; i < 4; i++)
#pragma unroll
        for (int j = 0; j < 4; j++)
#pragma unroll
            for (int r = 0; r < 4; r++) c[i][j][r] = 0.0f;

    const int a_kq = tid & 7;
    const int a_m  = tid >> 3;
    const int b_nr = tid >> 2;
    const int b_q  = tid & 3;

    const int NC = K / 32;

    auto load_chunk = [&](int k0, int buf) {
#pragma unroll
        for (int i = 0; i < 4; i++) {
            int m = a_m + 32 * i;
            int gm = m0 + m;
            int ok = (gm < M) ? 16 : 0;
            int gmc = (gm < M) ? gm : 0;
            cp_async16(&As[buf][m][a_kq * 4], A + (size_t)gmc * K + k0 + a_kq * 4, ok);
        }
#pragma unroll
        for (int i = 0; i < 2; i++) {
            int n = b_nr + 64 * i;
            cp_async16(&Bsn[buf][n][b_q * 8], Wt + (size_t)(n0 + n) * K + k0 + b_q * 8, 16);
        }
        CP_ASYNC_COMMIT();
    };

    load_chunk(0, 0);

    for (int cidx = 0; cidx < NC; cidx++) {
        const int buf = cidx & 1;
        if (cidx + 1 < NC) {
            load_chunk((cidx + 1) * 32, (cidx + 1) & 1);
            CP_ASYNC_WAIT1();
        } else {
            CP_ASYNC_WAIT0();
        }
        __syncthreads();

#pragma unroll
        for (int kk = 0; kk < 2; kk++) {
            uint32_t a[4][4], b[4][2];
#pragma unroll
            for (int mf = 0; mf < 4; mf++) {
                int m = wm * 64 + mf * 16 + g;
                float2 f0 = *(const float2*)&As[buf][m][kk * 16 + 2 * tg];
                float2 f1 = *(const float2*)&As[buf][m + 8][kk * 16 + 2 * tg];
                float2 f2 = *(const float2*)&As[buf][m][kk * 16 + 2 * tg + 8];
                float2 f3 = *(const float2*)&As[buf][m + 8][kk * 16 + 2 * tg + 8];
                __half2 h0 = __floats2half2_rn(f0.x, f0.y);
                __half2 h1 = __floats2half2_rn(f1.x, f1.y);
                __half2 h2 = __floats2half2_rn(f2.x, f2.y);
                __half2 h3 = __floats2half2_rn(f3.x, f3.y);
                a[mf][0] = *(uint32_t*)&h0;
                a[mf][1] = *(uint32_t*)&h1;
                a[mf][2] = *(uint32_t*)&h2;
                a[mf][3] = *(uint32_t*)&h3;
            }
#pragma unroll
            for (int nf = 0; nf < 4; nf++) {
                int n = wn * 32 + nf * 8 + g;
                b[nf][0] = *(const uint32_t*)&Bsn[buf][n][kk * 16 + 2 * tg];
                b[nf][1] = *(const uint32_t*)&Bsn[buf][n][kk * 16 + 2 * tg + 8];
            }
#pragma unroll
            for (int mf = 0; mf < 4; mf++)
#pragma unroll
                for (int nf = 0; nf < 4; nf++)
                    mma_f16(c[mf][nf], a[mf], b[nf]);
        }
        __syncthreads();
    }

#pragma unroll
    for (int mf = 0; mf < 4; mf++) {
        const int r0 = m0 + wm * 64 + mf * 16 + g;
        const int r1 = r0 + 8;
#pragma unroll
        for (int nf = 0; nf < 4; nf++) {
            const int cb = n0 + wn * 32 + nf * 8 + 2 * tg;
            const float bx = bias[cb], by = bias[cb + 1];
            if (r0 < M) {
                __half2 o = __floats2half2_rn(c[mf][nf][0] + bx, c[mf][nf][1] + by);
                *(__half2*)(C + (size_t)r0 * N + cb) = o;
            }
            if (r1 < M) {
                __half2 o = __floats2half2_rn(c[mf][nf][2] + bx, c[mf][nf][3] + by);
                *(__half2*)(C + (size_t)r1 * N + cb) = o;
            }
        }
    }
}

// ---------------------------------------------------------------------------
// fp16 GEMM for the query-path projections — round-14 proven. Unchanged.
// ---------------------------------------------------------------------------
__global__ __launch_bounds__(256, 4)
void gemm_f16q(const float* __restrict__ A, const __half* __restrict__ Bt,
               const float* __restrict__ bias, const float* __restrict__ resid,
               float* __restrict__ C, int M, int N, int K)
{
    __shared__ __half As[64][40];
    __shared__ __half Bsn[128][40];

    const int tid  = threadIdx.x;
    const int lane = tid & 31;
    const int wid  = tid >> 5;
    const int wm   = wid >> 2;
    const int wn   = wid & 3;
    const int g    = lane >> 2;
    const int tg   = lane & 3;
    const int m0   = blockIdx.y * 64;
    const int n0   = blockIdx.x * 128;

    float c[2][4][4];
#pragma unroll
    for (int i = 0; i < 2; i++)
#pragma unroll
        for (int j = 0; j < 4; j++)
#pragma unroll
            for (int r = 0; r < 4; r++) c[i][j][r] = 0.0f;

    const int a_kq = tid & 7;
    const int a_m  = tid >> 3;
    const int b_nr = tid >> 2;
    const int b_q  = tid & 3;

    for (int k0 = 0; k0 < K; k0 += 32) {
#pragma unroll
        for (int i = 0; i < 2; i++) {
            int m = a_m + 32 * i;
            float4 v = make_float4(0.f, 0.f, 0.f, 0.f);
            if (m0 + m < M) v = *(const float4*)(A + (size_t)(m0 + m) * K + k0 + a_kq * 4);
            __half2 h01 = __floats2half2_rn(v.x, v.y);
            __half2 h23 = __floats2half2_rn(v.z, v.w);
            uint2 pk;
            pk.x = *(uint32_t*)&h01;
            pk.y = *(uint32_t*)&h23;
            *(uint2*)&As[m][a_kq * 4] = pk;
        }
#pragma unroll
        for (int i = 0; i < 2; i++) {
            int n = b_nr + 64 * i;
            uint4 v = *(const uint4*)(Bt + (size_t)(n0 + n) * K + k0 + b_q * 8);
            *(uint4*)&Bsn[n][b_q * 8] = v;
        }
        __syncthreads();

#pragma unroll
        for (int kk = 0; kk < 2; kk++) {
            uint32_t a[2][4], b[4][2];
#pragma unroll
            for (int mf = 0; mf < 2; mf++) {
                int m = wm * 32 + mf * 16 + g;
                a[mf][0] = *(const uint32_t*)&As[m][kk * 16 + 2 * tg];
                a[mf][1] = *(const uint32_t*)&As[m + 8][kk * 16 + 2 * tg];
                a[mf][2] = *(const uint32_t*)&As[m][kk * 16 + 2 * tg + 8];
                a[mf][3] = *(const uint32_t*)&As[m + 8][kk * 16 + 2 * tg + 8];
            }
#pragma unroll
            for (int nf = 0; nf < 4; nf++) {
                int n = wn * 32 + nf * 8 + g;
                b[nf][0] = *(const uint32_t*)&Bsn[n][kk * 16 + 2 * tg];
                b[nf][1] = *(const uint32_t*)&Bsn[n][kk * 16 + 2 * tg + 8];
            }
#pragma unroll
            for (int mf = 0; mf < 2; mf++)
#pragma unroll
                for (int nf = 0; nf < 4; nf++)
                    mma_f16(c[mf][nf], a[mf], b[nf]);
        }
        __syncthreads();
    }

#pragma unroll
    for (int mf = 0; mf < 2; mf++) {
        const int r0 = m0 + wm * 32 + mf * 16 + g;
        const int r1 = r0 + 8;
#pragma unroll
        for (int nf = 0; nf < 4; nf++) {
            const int cb = n0 + wn * 32 + nf * 8 + 2 * tg;
            const float bx = bias[cb], by = bias[cb + 1];
            if (r0 < M) {
                float2 o = make_float2(c[mf][nf][0] + bx, c[mf][nf][1] + by);
                if (resid) {
                    const float2 rr = *(const float2*)(resid + (size_t)r0 * N + cb);
                    o.x += rr.x; o.y += rr.y;
                }
                *(float2*)(C + (size_t)r0 * N + cb) = o;
            }
            if (r1 < M) {
                float2 o = make_float2(c[mf][nf][2] + bx, c[mf][nf][3] + by);
                if (resid) {
                    const float2 rr = *(const float2*)(resid + (size_t)r1 * N + cb);
                    o.x += rr.x; o.y += rr.y;
                }
                *(float2*)(C + (size_t)r1 * N + cb) = o;
            }
        }
    }
}

// ---------------------------------------------------------------------------
// Fused softmax + deformable sampling — instruction-diet version:
//  * softmax via __shfl_xor butterfly within 16-lane head groups (no smem)
//  * sampling locs computed directly from float2 loads (no s_loc/s_lg stage,
//    one barrier instead of two)
//  * s_idx holds BYTE offsets (id*512) -> inner loop is LDS + IADD + LDG
// Gather structure identical to the proven round-13 kernel.
// ---------------------------------------------------------------------------
__global__ __launch_bounds__(128, 12)
void msda_sample(const float* __restrict__ offlg, const float* __restrict__ ref,
                 const __half* __restrict__ v, float* __restrict__ mid)
{
    const int lvlH[NLn]     = {92, 46, 23, 12};
    const int lvlW[NLn]     = {160, 80, 40, 20};
    const int lvlStart[NLn] = {0, 14720, 18400, 19320};

    const int row = blockIdx.x;
    const int b   = row / Qn;
    const int t   = threadIdx.x;   // 0..127 == sample id

    __shared__ int4   s_idx[128];   // byte offsets of 4 corners
    __shared__ float4 s_wgt[128];   // premultiplied corner weights

    // ---- per-sample precompute (no staging barriers) ----
    {
        const float lg = offlg[(size_t)row * 384 + 256 + t];
        // softmax over the 16 samples of this head via butterfly shfl
        float m = lg;
#pragma unroll
        for (int mask = 1; mask < 16; mask <<= 1)
            m = fmaxf(m, __shfl_xor_sync(0xffffffffu, m, mask));
        const float e = __expf(lg - m);
        float sum = e;
#pragma unroll
        for (int mask = 1; mask < 16; mask <<= 1)
            sum += __shfl_xor_sync(0xffffffffu, sum, mask);
        const float w = e / sum;

        const int l = (t >> 2) & 3;
        const int Hl = lvlH[l], Wl = lvlW[l], base = lvlStart[l];
        const float2 off2 = *(const float2*)(offlg + (size_t)row * 384 + 2 * t);
        const float2 ref2 = *(const float2*)(ref + ((size_t)row * NLn + l) * 2);
        const float x = ref2.x * (float)Wl - 0.5f + off2.x;
        const float y = ref2.y * (float)Hl - 0.5f + off2.y;

        const float xf = floorf(x), yf = floorf(y);
        const float wx = x - xf, wy = y - yf;
        const int x0 = (int)xf, y0 = (int)yf, x1 = x0 + 1, y1 = y0 + 1;

        const bool vx0 = (x0 >= 0) & (x0 < Wl), vx1 = (x1 >= 0) & (x1 < Wl);
        const bool vy0 = (y0 >= 0) & (y0 < Hl), vy1 = (y1 >= 0) & (y1 < Hl);
        const int xc0 = min(max(x0, 0), Wl - 1), xc1 = min(max(x1, 0), Wl - 1);
        const int yc0 = min(max(y0, 0), Hl - 1), yc1 = min(max(y1, 0), Hl - 1);

        int4 id;   // byte offsets: element index * En * sizeof(half) = *512
        id.x = (base + yc0 * Wl + xc0) << 9;
        id.y = (base + yc0 * Wl + xc1) << 9;
        id.z = (base + yc1 * Wl + xc0) << 9;
        id.w = (base + yc1 * Wl + xc1) << 9;
        s_idx[t] = id;
        float4 ww;
        ww.x = (vy0 & vx0) ? w * (1.f - wy) * (1.f - wx) : 0.f;
        ww.y = (vy0 & vx1) ? w * (1.f - wy) * wx : 0.f;
        ww.z = (vy1 & vx0) ? w * wy * (1.f - wx) : 0.f;
        ww.w = (vy1 & vx1) ? w * wy * wx : 0.f;
        s_wgt[t] = ww;
    }
    __syncthreads();

    const int h  = t >> 4;          // 0..7
    const int dp = t & 15;          // channel pair 0..15
    const char* __restrict__ vbase =
        (const char*)v + ((size_t)b * Sn * En + h * HDn + dp * 2) * sizeof(__half);

    float accx = 0.0f, accy = 0.0f;
#pragma unroll
    for (int s = 0; s < 16; s++) {
        const int si = h * 16 + s;
        const int4   id = s_idx[si];
        const float4 ww = s_wgt[si];
        float2 f0 = __half22float2(*(const __half2*)(vbase + id.x));
        float2 f1 = __half22float2(*(const __half2*)(vbase + id.y));
        float2 f2 = __half22float2(*(const __half2*)(vbase + id.z));
        float2 f3 = __half22float2(*(const __half2*)(vbase + id.w));
        accx += ww.x * f0.x + ww.y * f1.x + ww.z * f2.x + ww.w * f3.x;
        accy += ww.x * f0.y + ww.y * f1.y + ww.z * f2.y + ww.w * f3.y;
    }

    *(float2*)(mid + (size_t)row * En + h * HDn + dp * 2) = make_float2(accx, accy);
}

// ---------------------------------------------------------------------------
extern "C" void kernel_launch(void* const* d_in, const int* in_sizes, int n_in,
                              void* d_out, int out_size)
{
    const float* query  = (const float*)d_in[0];
    const float* value  = (const float*)d_in[1];
    const float* refpts = (const float*)d_in[2];
    const float* W_off  = (const float*)d_in[4];
    const float* b_off  = (const float*)d_in[5];
    const float* W_attn = (const float*)d_in[6];
    const float* b_attn = (const float*)d_in[7];
    const float* W_v    = (const float*)d_in[8];
    const float* b_v    = (const float*)d_in[9];
    const float* W_out  = (const float*)d_in[10];
    const float* b_out  = (const float*)d_in[11];
    float* out = (float*)d_out;

    void *pvh, *pwt, *pwot, *pwcq, *pbc, *polg, *pmid;
    cudaGetSymbolAddress(&pvh, g_vh);
    cudaGetSymbolAddress(&pwt, g_wt);
    cudaGetSymbolAddress(&pwot, g_wot);
    cudaGetSymbolAddress(&pwcq, g_wcq);
    cudaGetSymbolAddress(&pbc, g_bc);
    cudaGetSymbolAddress(&polg, g_offlg);
    cudaGetSymbolAddress(&pmid, g_mid);
    __half* vh_s  = (__half*)pvh;
    __half* wt_s  = (__half*)pwt;
    __half* wot_s = (__half*)pwot;
    __half* wcq_s = (__half*)pwcq;
    float* bc_s   = (float*)pbc;
    float* olg_s  = (float*)polg;
    float* mid_s  = (float*)pmid;

    // 0) fused weight prep (transpose + fp16 convert + bias concat)
    prep_weights<<<225, dim3(32, 8)>>>(W_v, W_out, W_off, b_off, W_attn, b_attn,
                                       wt_s, wot_s, wcq_s, bc_s);

    // 1) value projection: [156480,256] @ [256,256]  (fp16 MMA, cp.async)
    {
        dim3 grid(En / 128, (Mv + 127) / 128);
        gemm_f16v<<<grid, 256>>>(value, wt_s, b_v, vh_s, Mv, En, En);
    }
    // 2) combined offset+logit projection: [7200,256] @ [256,384]  (fp16, BM=64)
    {
        dim3 grid(384 / 128, (BQn + 63) / 64);
        gemm_f16q<<<grid, 256>>>(query, wcq_s, bc_s, nullptr, olg_s, BQn, 384, En);
    }
    // 3) softmax + deformable bilinear sampling (shfl softmax, byte offsets)
    msda_sample<<<BQn, 128>>>(olg_s, refpts, vh_s, mid_s);
    // 4) output projection + residual: [7200,256] @ [256,256] + query  (fp16, BM=64)
    {
        dim3 grid(En / 128, (BQn + 63) / 64);
        gemm_f16q<<<grid, 256>>>(mid_s, wot_s, b_out, query, out, BQn, En, En);
    }
}

// round 17
// speedup vs baseline: 2.2625x; 1.0415x over previous
#include <cuda_runtime.h>
#include <cuda_fp16.h>
#include <cstdint>
#include <cstddef>

// Problem constants
#define Bn   8
#define Qn   900
#define En   256
#define NHn  8
#define HDn  32
#define NLn  4
#define NPn  4
#define Sn   19560
#define BQn  (Bn * Qn)          // 7200
#define Mv   (Bn * Sn)          // 156480

#define QPROJ_BLOCKS 339        // 3 x 113 (BM=64 tiles over [7200,384])
#define VP_BLOCKS    2446       // 2 x 1223 (BM=128 tiles over [156480,256])

// Scratch (static device globals)
__device__ __half g_vh[(size_t)Bn * Sn * En];    // projected values [B,S,E] fp16
__device__ __half g_wt[(size_t)En * En];         // W_v^T   half [n][k]
__device__ __half g_wot[(size_t)En * En];        // W_out^T half [n][k]
__device__ __half g_wcq[(size_t)384 * En];       // [W_off | W_attn]^T half [n=384][k]
__device__ float g_bc[384];                      // b_off || b_attn
__device__ float g_offlg[(size_t)BQn * 384];     // [off(256) | logits(128)] per row
__device__ __half g_mid[(size_t)BQn * En];       // sampled output, fp16

// ---------------------------------------------------------------------------
// cp.async helpers
// ---------------------------------------------------------------------------
__device__ __forceinline__ void cp_async16(void* smem_dst, const void* gsrc, int src_bytes) {
    uint32_t d = (uint32_t)__cvta_generic_to_shared(smem_dst);
    asm volatile("cp.async.cg.shared.global [%0], [%1], 16, %2;"
                 :: "r"(d), "l"(gsrc), "r"(src_bytes) : "memory");
}
#define CP_ASYNC_COMMIT() asm volatile("cp.async.commit_group;" ::: "memory")
#define CP_ASYNC_WAIT1()  asm volatile("cp.async.wait_group 1;" ::: "memory")
#define CP_ASYNC_WAIT0()  asm volatile("cp.async.wait_group 0;" ::: "memory")

// ---------------------------------------------------------------------------
// Fused prologue: transpose+fp16-convert weights + bias concat (proven).
// ---------------------------------------------------------------------------
__global__ void prep_weights(const float* __restrict__ W_v, const float* __restrict__ W_out,
                             const float* __restrict__ W_off, const float* __restrict__ b_off,
                             const float* __restrict__ W_attn, const float* __restrict__ b_attn,
                             __half* __restrict__ Wvt, __half* __restrict__ Wot,
                             __half* __restrict__ Wcq, float* __restrict__ bc)
{
    const int blk = blockIdx.x;
    const int tx = threadIdx.x, ty = threadIdx.y;   // 32 x 8

    if (blk == 224) {
        for (int i = ty * 32 + tx; i < 384; i += 256)
            bc[i] = (i < 256) ? b_off[i] : b_attn[i - 256];
        return;
    }

    __shared__ float tile[32][33];
    const float* src;
    __half* dst;
    int bx, by, srcN;
    if (blk < 64)       { src = W_v;    dst = Wvt;                 int u = blk;       bx = (u & 7) * 32; by = (u >> 3) * 32; srcN = 256; }
    else if (blk < 128) { src = W_out;  dst = Wot;                 int u = blk - 64;  bx = (u & 7) * 32; by = (u >> 3) * 32; srcN = 256; }
    else if (blk < 192) { src = W_off;  dst = Wcq;                 int u = blk - 128; bx = (u & 7) * 32; by = (u >> 3) * 32; srcN = 256; }
    else                { src = W_attn; dst = Wcq + (size_t)256 * 256; int u = blk - 192; bx = (u & 3) * 32; by = (u >> 2) * 32; srcN = 128; }

#pragma unroll
    for (int i = 0; i < 32; i += 8)
        tile[ty + i][tx] = src[(size_t)(by + ty + i) * srcN + bx + tx];
    __syncthreads();
#pragma unroll
    for (int i = 0; i < 32; i += 8)
        dst[(size_t)(bx + ty + i) * 256 + by + tx] = __float2half_rn(tile[tx][ty + i]);
}

// ---------------------------------------------------------------------------
// fp16 mma.sync helper
// ---------------------------------------------------------------------------
__device__ __forceinline__ void mma_f16(float* c, const uint32_t* a, const uint32_t* b) {
    asm volatile(
        "mma.sync.aligned.m16n8k16.row.col.f32.f16.f16.f32 "
        "{%0,%1,%2,%3}, {%4,%5,%6,%7}, {%8,%9}, {%0,%1,%2,%3};"
        : "+f"(c[0]), "+f"(c[1]), "+f"(c[2]), "+f"(c[3])
        : "r"(a[0]), "r"(a[1]), "r"(a[2]), "r"(a[3]), "r"(b[0]), "r"(b[1]));
}

// ---------------------------------------------------------------------------
// Shared-memory layouts for the fused kernel (union)
// ---------------------------------------------------------------------------
struct VPShm {
    float  As[2][128][40];     // fp32 A stage (40960 B)
    __half Bsn[2][128][56];    // half B stage (28672 B)
};
struct QPShm {
    __half As[64][40];         // half A stage (5120 B)
    __half Bsn[128][40];       // half B stage (10240 B)
};
union FusedShm {
    VPShm v;
    QPShm q;
};

// ---------------------------------------------------------------------------
// VP body (cp.async double-buffered fp16 GEMM) — round-15 proven code, with
// block coords as parameters.
// ---------------------------------------------------------------------------
__device__ __forceinline__
void vp_body(VPShm& sm, int bx, int by,
             const float* __restrict__ A, const __half* __restrict__ Wt,
             const float* __restrict__ bias, __half* __restrict__ C)
{
    const int M = Mv, N = En, K = En;
    const int tid  = threadIdx.x;
    const int lane = tid & 31;
    const int wid  = tid >> 5;
    const int wm   = wid >> 2;
    const int wn   = wid & 3;
    const int g    = lane >> 2;
    const int tg   = lane & 3;
    const int m0   = by * 128;
    const int n0   = bx * 128;

    float c[4][4][4];
#pragma unroll
    for (int i = 0; i < 4; i++)
#pragma unroll
        for (int j = 0; j < 4; j++)
#pragma unroll
            for (int r = 0; r < 4; r++) c[i][j][r] = 0.0f;

    const int a_kq = tid & 7;
    const int a_m  = tid >> 3;
    const int b_nr = tid >> 2;
    const int b_q  = tid & 3;

    const int NC = K / 32;

    auto load_chunk = [&](int k0, int buf) {
#pragma unroll
        for (int i = 0; i < 4; i++) {
            int m = a_m + 32 * i;
            int gm = m0 + m;
            int ok = (gm < M) ? 16 : 0;
            int gmc = (gm < M) ? gm : 0;
            cp_async16(&sm.As[buf][m][a_kq * 4], A + (size_t)gmc * K + k0 + a_kq * 4, ok);
        }
#pragma unroll
        for (int i = 0; i < 2; i++) {
            int n = b_nr + 64 * i;
            cp_async16(&sm.Bsn[buf][n][b_q * 8], Wt + (size_t)(n0 + n) * K + k0 + b_q * 8, 16);
        }
        CP_ASYNC_COMMIT();
    };

    load_chunk(0, 0);

    for (int cidx = 0; cidx < NC; cidx++) {
        const int buf = cidx & 1;
        if (cidx + 1 < NC) {
            load_chunk((cidx + 1) * 32, (cidx + 1) & 1);
            CP_ASYNC_WAIT1();
        } else {
            CP_ASYNC_WAIT0();
        }
        __syncthreads();

#pragma unroll
        for (int kk = 0; kk < 2; kk++) {
            uint32_t a[4][4], b[4][2];
#pragma unroll
            for (int mf = 0; mf < 4; mf++) {
                int m = wm * 64 + mf * 16 + g;
                float2 f0 = *(const float2*)&sm.As[buf][m][kk * 16 + 2 * tg];
                float2 f1 = *(const float2*)&sm.As[buf][m + 8][kk * 16 + 2 * tg];
                float2 f2 = *(const float2*)&sm.As[buf][m][kk * 16 + 2 * tg + 8];
                float2 f3 = *(const float2*)&sm.As[buf][m + 8][kk * 16 + 2 * tg + 8];
                __half2 h0 = __floats2half2_rn(f0.x, f0.y);
                __half2 h1 = __floats2half2_rn(f1.x, f1.y);
                __half2 h2 = __floats2half2_rn(f2.x, f2.y);
                __half2 h3 = __floats2half2_rn(f3.x, f3.y);
                a[mf][0] = *(uint32_t*)&h0;
                a[mf][1] = *(uint32_t*)&h1;
                a[mf][2] = *(uint32_t*)&h2;
                a[mf][3] = *(uint32_t*)&h3;
            }
#pragma unroll
            for (int nf = 0; nf < 4; nf++) {
                int n = wn * 32 + nf * 8 + g;
                b[nf][0] = *(const uint32_t*)&sm.Bsn[buf][n][kk * 16 + 2 * tg];
                b[nf][1] = *(const uint32_t*)&sm.Bsn[buf][n][kk * 16 + 2 * tg + 8];
            }
#pragma unroll
            for (int mf = 0; mf < 4; mf++)
#pragma unroll
                for (int nf = 0; nf < 4; nf++)
                    mma_f16(c[mf][nf], a[mf], b[nf]);
        }
        __syncthreads();
    }

#pragma unroll
    for (int mf = 0; mf < 4; mf++) {
        const int r0 = m0 + wm * 64 + mf * 16 + g;
        const int r1 = r0 + 8;
#pragma unroll
        for (int nf = 0; nf < 4; nf++) {
            const int cb = n0 + wn * 32 + nf * 8 + 2 * tg;
            const float bx_ = bias[cb], by_ = bias[cb + 1];
            if (r0 < M) {
                __half2 o = __floats2half2_rn(c[mf][nf][0] + bx_, c[mf][nf][1] + by_);
                *(__half2*)(C + (size_t)r0 * N + cb) = o;
            }
            if (r1 < M) {
                __half2 o = __floats2half2_rn(c[mf][nf][2] + bx_, c[mf][nf][3] + by_);
                *(__half2*)(C + (size_t)r1 * N + cb) = o;
            }
        }
    }
}

// ---------------------------------------------------------------------------
// Q-proj body (fp32 A, half weights) — round-14 proven gemm_f16q code with
// block coords as parameters. N=384, BM=64.
// ---------------------------------------------------------------------------
__device__ __forceinline__
void qproj_body(QPShm& sm, int bxb, int byb,
                const float* __restrict__ A, const __half* __restrict__ Bt,
                const float* __restrict__ bias, float* __restrict__ C)
{
    const int M = BQn, N = 384, K = En;
    const int tid  = threadIdx.x;
    const int lane = tid & 31;
    const int wid  = tid >> 5;
    const int wm   = wid >> 2;
    const int wn   = wid & 3;
    const int g    = lane >> 2;
    const int tg   = lane & 3;
    const int m0   = byb * 64;
    const int n0   = bxb * 128;

    float c[2][4][4];
#pragma unroll
    for (int i = 0; i < 2; i++)
#pragma unroll
        for (int j = 0; j < 4; j++)
#pragma unroll
            for (int r = 0; r < 4; r++) c[i][j][r] = 0.0f;

    const int a_kq = tid & 7;
    const int a_m  = tid >> 3;
    const int b_nr = tid >> 2;
    const int b_q  = tid & 3;

    for (int k0 = 0; k0 < K; k0 += 32) {
#pragma unroll
        for (int i = 0; i < 2; i++) {
            int m = a_m + 32 * i;
            float4 v = make_float4(0.f, 0.f, 0.f, 0.f);
            if (m0 + m < M) v = *(const float4*)(A + (size_t)(m0 + m) * K + k0 + a_kq * 4);
            __half2 h01 = __floats2half2_rn(v.x, v.y);
            __half2 h23 = __floats2half2_rn(v.z, v.w);
            uint2 pk;
            pk.x = *(uint32_t*)&h01;
            pk.y = *(uint32_t*)&h23;
            *(uint2*)&sm.As[m][a_kq * 4] = pk;
        }
#pragma unroll
        for (int i = 0; i < 2; i++) {
            int n = b_nr + 64 * i;
            uint4 v = *(const uint4*)(Bt + (size_t)(n0 + n) * K + k0 + b_q * 8);
            *(uint4*)&sm.Bsn[n][b_q * 8] = v;
        }
        __syncthreads();

#pragma unroll
        for (int kk = 0; kk < 2; kk++) {
            uint32_t a[2][4], b[4][2];
#pragma unroll
            for (int mf = 0; mf < 2; mf++) {
                int m = wm * 32 + mf * 16 + g;
                a[mf][0] = *(const uint32_t*)&sm.As[m][kk * 16 + 2 * tg];
                a[mf][1] = *(const uint32_t*)&sm.As[m + 8][kk * 16 + 2 * tg];
                a[mf][2] = *(const uint32_t*)&sm.As[m][kk * 16 + 2 * tg + 8];
                a[mf][3] = *(const uint32_t*)&sm.As[m + 8][kk * 16 + 2 * tg + 8];
            }
#pragma unroll
            for (int nf = 0; nf < 4; nf++) {
                int n = wn * 32 + nf * 8 + g;
                b[nf][0] = *(const uint32_t*)&sm.Bsn[n][kk * 16 + 2 * tg];
                b[nf][1] = *(const uint32_t*)&sm.Bsn[n][kk * 16 + 2 * tg + 8];
            }
#pragma unroll
            for (int mf = 0; mf < 2; mf++)
#pragma unroll
                for (int nf = 0; nf < 4; nf++)
                    mma_f16(c[mf][nf], a[mf], b[nf]);
        }
        __syncthreads();
    }

#pragma unroll
    for (int mf = 0; mf < 2; mf++) {
        const int r0 = m0 + wm * 32 + mf * 16 + g;
        const int r1 = r0 + 8;
#pragma unroll
        for (int nf = 0; nf < 4; nf++) {
            const int cb = n0 + wn * 32 + nf * 8 + 2 * tg;
            const float bx_ = bias[cb], by_ = bias[cb + 1];
            if (r0 < M) {
                float2 o = make_float2(c[mf][nf][0] + bx_, c[mf][nf][1] + by_);
                *(float2*)(C + (size_t)r0 * N + cb) = o;
            }
            if (r1 < M) {
                float2 o = make_float2(c[mf][nf][2] + bx_, c[mf][nf][3] + by_);
                *(float2*)(C + (size_t)r1 * N + cb) = o;
            }
        }
    }
}

// ---------------------------------------------------------------------------
// Fused vp + q-proj launch: blocks 0..338 run q-proj, 339..2784 run vp.
// ---------------------------------------------------------------------------
__global__ __launch_bounds__(256, 2)
void fused_proj(const float* __restrict__ value, const __half* __restrict__ Wvt,
                const float* __restrict__ b_v, __half* __restrict__ vh,
                const float* __restrict__ query, const __half* __restrict__ Wcq,
                const float* __restrict__ bc, float* __restrict__ olg)
{
    __shared__ FusedShm sm;
    const int bid = blockIdx.x;
    if (bid < QPROJ_BLOCKS) {
        qproj_body(sm.q, bid % 3, bid / 3, query, Wcq, bc, olg);
    } else {
        const int u = bid - QPROJ_BLOCKS;
        vp_body(sm.v, u & 1, u >> 1, value, Wvt, b_v, vh);
    }
}

// ---------------------------------------------------------------------------
// Out-proj GEMM with HALF A (mid) + fp32 residual — staging is direct copies.
// Fragment/epilogue structure identical to proven gemm_f16q.
// ---------------------------------------------------------------------------
__global__ __launch_bounds__(256, 4)
void gemm_f16qh(const __half* __restrict__ A, const __half* __restrict__ Bt,
                const float* __restrict__ bias, const float* __restrict__ resid,
                float* __restrict__ C, int M, int N, int K)
{
    __shared__ __half As[64][40];
    __shared__ __half Bsn[128][40];

    const int tid  = threadIdx.x;
    const int lane = tid & 31;
    const int wid  = tid >> 5;
    const int wm   = wid >> 2;
    const int wn   = wid & 3;
    const int g    = lane >> 2;
    const int tg   = lane & 3;
    const int m0   = blockIdx.y * 64;
    const int n0   = blockIdx.x * 128;

    float c[2][4][4];
#pragma unroll
    for (int i = 0; i < 2; i++)
#pragma unroll
        for (int j = 0; j < 4; j++)
#pragma unroll
            for (int r = 0; r < 4; r++) c[i][j][r] = 0.0f;

    const int a_nr = tid >> 2;          // 0..63 (A row)
    const int a_q  = tid & 3;           // uint4 in 32-k row
    const int b_nr = tid >> 2;
    const int b_q  = tid & 3;

    for (int k0 = 0; k0 < K; k0 += 32) {
        // A tile 64x32 half: direct copy
        {
            int gm = m0 + a_nr;
            uint4 v = make_uint4(0u, 0u, 0u, 0u);
            if (gm < M) v = *(const uint4*)(A + (size_t)gm * K + k0 + a_q * 8);
            *(uint4*)&As[a_nr][a_q * 8] = v;
        }
        // B tile 128x32 half: direct copy
#pragma unroll
        for (int i = 0; i < 2; i++) {
            int n = b_nr + 64 * i;
            uint4 v = *(const uint4*)(Bt + (size_t)(n0 + n) * K + k0 + b_q * 8);
            *(uint4*)&Bsn[n][b_q * 8] = v;
        }
        __syncthreads();

#pragma unroll
        for (int kk = 0; kk < 2; kk++) {
            uint32_t a[2][4], b[4][2];
#pragma unroll
            for (int mf = 0; mf < 2; mf++) {
                int m = wm * 32 + mf * 16 + g;
                a[mf][0] = *(const uint32_t*)&As[m][kk * 16 + 2 * tg];
                a[mf][1] = *(const uint32_t*)&As[m + 8][kk * 16 + 2 * tg];
                a[mf][2] = *(const uint32_t*)&As[m][kk * 16 + 2 * tg + 8];
                a[mf][3] = *(const uint32_t*)&As[m + 8][kk * 16 + 2 * tg + 8];
            }
#pragma unroll
            for (int nf = 0; nf < 4; nf++) {
                int n = wn * 32 + nf * 8 + g;
                b[nf][0] = *(const uint32_t*)&Bsn[n][kk * 16 + 2 * tg];
                b[nf][1] = *(const uint32_t*)&Bsn[n][kk * 16 + 2 * tg + 8];
            }
#pragma unroll
            for (int mf = 0; mf < 2; mf++)
#pragma unroll
                for (int nf = 0; nf < 4; nf++)
                    mma_f16(c[mf][nf], a[mf], b[nf]);
        }
        __syncthreads();
    }

#pragma unroll
    for (int mf = 0; mf < 2; mf++) {
        const int r0 = m0 + wm * 32 + mf * 16 + g;
        const int r1 = r0 + 8;
#pragma unroll
        for (int nf = 0; nf < 4; nf++) {
            const int cb = n0 + wn * 32 + nf * 8 + 2 * tg;
            const float bx = bias[cb], by = bias[cb + 1];
            if (r0 < M) {
                float2 o = make_float2(c[mf][nf][0] + bx, c[mf][nf][1] + by);
                const float2 rr = *(const float2*)(resid + (size_t)r0 * N + cb);
                o.x += rr.x; o.y += rr.y;
                *(float2*)(C + (size_t)r0 * N + cb) = o;
            }
            if (r1 < M) {
                float2 o = make_float2(c[mf][nf][2] + bx, c[mf][nf][3] + by);
                const float2 rr = *(const float2*)(resid + (size_t)r1 * N + cb);
                o.x += rr.x; o.y += rr.y;
                *(float2*)(C + (size_t)r1 * N + cb) = o;
            }
        }
    }
}

// ---------------------------------------------------------------------------
// Fused softmax + deformable sampling — round-16 proven; writes half2 mid
// (same rounding the downstream GEMM applied anyway -> numerically identical).
// ---------------------------------------------------------------------------
__global__ __launch_bounds__(128, 12)
void msda_sample(const float* __restrict__ offlg, const float* __restrict__ ref,
                 const __half* __restrict__ v, __half* __restrict__ mid)
{
    const int lvlH[NLn]     = {92, 46, 23, 12};
    const int lvlW[NLn]     = {160, 80, 40, 20};
    const int lvlStart[NLn] = {0, 14720, 18400, 19320};

    const int row = blockIdx.x;
    const int b   = row / Qn;
    const int t   = threadIdx.x;   // 0..127 == sample id

    __shared__ int4   s_idx[128];
    __shared__ float4 s_wgt[128];

    {
        const float lg = offlg[(size_t)row * 384 + 256 + t];
        float m = lg;
#pragma unroll
        for (int mask = 1; mask < 16; mask <<= 1)
            m = fmaxf(m, __shfl_xor_sync(0xffffffffu, m, mask));
        const float e = __expf(lg - m);
        float sum = e;
#pragma unroll
        for (int mask = 1; mask < 16; mask <<= 1)
            sum += __shfl_xor_sync(0xffffffffu, sum, mask);
        const float w = e / sum;

        const int l = (t >> 2) & 3;
        const int Hl = lvlH[l], Wl = lvlW[l], base = lvlStart[l];
        const float2 off2 = *(const float2*)(offlg + (size_t)row * 384 + 2 * t);
        const float2 ref2 = *(const float2*)(ref + ((size_t)row * NLn + l) * 2);
        const float x = ref2.x * (float)Wl - 0.5f + off2.x;
        const float y = ref2.y * (float)Hl - 0.5f + off2.y;

        const float xf = floorf(x), yf = floorf(y);
        const float wx = x - xf, wy = y - yf;
        const int x0 = (int)xf, y0 = (int)yf, x1 = x0 + 1, y1 = y0 + 1;

        const bool vx0 = (x0 >= 0) & (x0 < Wl), vx1 = (x1 >= 0) & (x1 < Wl);
        const bool vy0 = (y0 >= 0) & (y0 < Hl), vy1 = (y1 >= 0) & (y1 < Hl);
        const int xc0 = min(max(x0, 0), Wl - 1), xc1 = min(max(x1, 0), Wl - 1);
        const int yc0 = min(max(y0, 0), Hl - 1), yc1 = min(max(y1, 0), Hl - 1);

        int4 id;
        id.x = (base + yc0 * Wl + xc0) << 9;
        id.y = (base + yc0 * Wl + xc1) << 9;
        id.z = (base + yc1 * Wl + xc0) << 9;
        id.w = (base + yc1 * Wl + xc1) << 9;
        s_idx[t] = id;
        float4 ww;
        ww.x = (vy0 & vx0) ? w * (1.f - wy) * (1.f - wx) : 0.f;
        ww.y = (vy0 & vx1) ? w * (1.f - wy) * wx : 0.f;
        ww.z = (vy1 & vx0) ? w * wy * (1.f - wx) : 0.f;
        ww.w = (vy1 & vx1) ? w * wy * wx : 0.f;
        s_wgt[t] = ww;
    }
    __syncthreads();

    const int h  = t >> 4;
    const int dp = t & 15;
    const char* __restrict__ vbase =
        (const char*)v + ((size_t)b * Sn * En + h * HDn + dp * 2) * sizeof(__half);

    float accx = 0.0f, accy = 0.0f;
#pragma unroll
    for (int s = 0; s < 16; s++) {
        const int si = h * 16 + s;
        const int4   id = s_idx[si];
        const float4 ww = s_wgt[si];
        float2 f0 = __half22float2(*(const __half2*)(vbase + id.x));
        float2 f1 = __half22float2(*(const __half2*)(vbase + id.y));
        float2 f2 = __half22float2(*(const __half2*)(vbase + id.z));
        float2 f3 = __half22float2(*(const __half2*)(vbase + id.w));
        accx += ww.x * f0.x + ww.y * f1.x + ww.z * f2.x + ww.w * f3.x;
        accy += ww.x * f0.y + ww.y * f1.y + ww.z * f2.y + ww.w * f3.y;
    }

    *(__half2*)(mid + (size_t)row * En + h * HDn + dp * 2) = __floats2half2_rn(accx, accy);
}

// ---------------------------------------------------------------------------
extern "C" void kernel_launch(void* const* d_in, const int* in_sizes, int n_in,
                              void* d_out, int out_size)
{
    const float* query  = (const float*)d_in[0];
    const float* value  = (const float*)d_in[1];
    const float* refpts = (const float*)d_in[2];
    const float* W_off  = (const float*)d_in[4];
    const float* b_off  = (const float*)d_in[5];
    const float* W_attn = (const float*)d_in[6];
    const float* b_attn = (const float*)d_in[7];
    const float* W_v    = (const float*)d_in[8];
    const float* b_v    = (const float*)d_in[9];
    const float* W_out  = (const float*)d_in[10];
    const float* b_out  = (const float*)d_in[11];
    float* out = (float*)d_out;

    void *pvh, *pwt, *pwot, *pwcq, *pbc, *polg, *pmid;
    cudaGetSymbolAddress(&pvh, g_vh);
    cudaGetSymbolAddress(&pwt, g_wt);
    cudaGetSymbolAddress(&pwot, g_wot);
    cudaGetSymbolAddress(&pwcq, g_wcq);
    cudaGetSymbolAddress(&pbc, g_bc);
    cudaGetSymbolAddress(&polg, g_offlg);
    cudaGetSymbolAddress(&pmid, g_mid);
    __half* vh_s  = (__half*)pvh;
    __half* wt_s  = (__half*)pwt;
    __half* wot_s = (__half*)pwot;
    __half* wcq_s = (__half*)pwcq;
    float* bc_s   = (float*)pbc;
    float* olg_s  = (float*)polg;
    __half* mid_s = (__half*)pmid;

    // 0) fused weight prep (transpose + fp16 convert + bias concat)
    prep_weights<<<225, dim3(32, 8)>>>(W_v, W_out, W_off, b_off, W_attn, b_attn,
                                       wt_s, wot_s, wcq_s, bc_s);

    // 1) fused value projection + offset/logit projection (one launch)
    fused_proj<<<QPROJ_BLOCKS + VP_BLOCKS, 256>>>(value, wt_s, b_v, vh_s,
                                                  query, wcq_s, bc_s, olg_s);

    // 2) softmax + deformable bilinear sampling (half2 gathers, half mid)
    msda_sample<<<BQn, 128>>>(olg_s, refpts, vh_s, mid_s);

    // 3) output projection + residual: [7200,256] @ [256,256] + query
    {
        dim3 grid(En / 128, (BQn + 63) / 64);
        gemm_f16qh<<<grid, 256>>>(mid_s, wot_s, b_out, query, out, BQn, En, En);
    }
}